// round 6
// baseline (speedup 1.0000x reference)
#include <cuda_runtime.h>
#include <cstdint>

#define BB 2
#define NH 32
#define SP 16384   // T*H*W
#define NN 1024
#define TBL 6727   // 7*31*31
#define EPS 1e-5f
#define PSTRD 68   // P/Vt row stride in floats

typedef unsigned long long ull;

// ---- scratch (device globals; no allocation allowed) ----
__device__ float g_raw[3][BB][128][SP];   // projected q/k/v pre-norm
__device__ float g_mu[3][BB][NH];
__device__ float g_rs[3][BB][NH];
__device__ float g_qp[BB][NH][NN][4];     // pooled normalized queries
__device__ float g_kp[BB][NH][NN][4];     // pooled normalized keys
__device__ float g_vt[BB][NH][64][NN];    // V^T fp32 (tf32-rounded): [c][n]

__device__ __forceinline__ void ffma2(ull& d, ull a, ull b) {
  asm("fma.rn.f32x2 %0, %1, %2, %0;" : "+l"(d) : "l"(a), "l"(b));
}
__device__ __forceinline__ ull pack2(float lo, float hi) {
  ull r; asm("mov.b64 %0, {%1, %2};" : "=l"(r) : "f"(lo), "f"(hi)); return r;
}
__device__ __forceinline__ void unpack2(ull v, float& lo, float& hi) {
  asm("mov.b64 {%0, %1}, %2;" : "=f"(lo), "=f"(hi) : "l"(v));
}
__device__ __forceinline__ float tf32r(float x) {
  uint32_t u; asm("cvt.rna.tf32.f32 %0, %1;" : "=r"(u) : "f"(x));
  return __uint_as_float(u);
}
__device__ __forceinline__ void mma_tf32(float* c, uint32_t a0, uint32_t a1,
                                         uint32_t a2, uint32_t a3,
                                         uint32_t b0, uint32_t b1) {
  asm volatile(
      "mma.sync.aligned.m16n8k8.row.col.f32.tf32.tf32.f32 "
      "{%0,%1,%2,%3}, {%4,%5,%6,%7}, {%8,%9}, {%0,%1,%2,%3};"
      : "+f"(c[0]), "+f"(c[1]), "+f"(c[2]), "+f"(c[3])
      : "r"(a0), "r"(a1), "r"(a2), "r"(a3), "r"(b0), "r"(b1));
}

// ============================================================
// K1: pointwise projections (f32x2)
// ============================================================
__global__ __launch_bounds__(256) void proj_kernel(
    const float* __restrict__ x,
    const float* __restrict__ Wq, const float* __restrict__ Wk,
    const float* __restrict__ Wv) {
  const int z = blockIdx.z, b = blockIdx.y;
  const int s0 = blockIdx.x * 64;
  const float* __restrict__ Wm = (z == 0) ? Wq : (z == 1 ? Wk : Wv);
  __shared__ float Ws[16][128];
  __shared__ float xs[16][64];
  const int t = threadIdx.x, tx = t & 15, ty = t >> 4;
  ull acc[8][2];
#pragma unroll
  for (int i = 0; i < 8; i++) { acc[i][0] = 0ull; acc[i][1] = 0ull; }
  const float* xb = x + (size_t)b * 128 * SP;
  for (int kc = 0; kc < 128; kc += 16) {
    {
      int o = t >> 1, koff = (t & 1) * 8;
      const float* wp = Wm + o * 128 + kc + koff;
      float4 w0 = *(const float4*)wp;
      float4 w1 = *(const float4*)(wp + 4);
      Ws[koff + 0][o] = w0.x; Ws[koff + 1][o] = w0.y;
      Ws[koff + 2][o] = w0.z; Ws[koff + 3][o] = w0.w;
      Ws[koff + 4][o] = w1.x; Ws[koff + 5][o] = w1.y;
      Ws[koff + 6][o] = w1.z; Ws[koff + 7][o] = w1.w;
    }
    *(float4*)&xs[ty][tx * 4] = *(const float4*)&xb[(size_t)(kc + ty) * SP + s0 + tx * 4];
    __syncthreads();
#pragma unroll
    for (int k = 0; k < 16; k++) {
      float4 a0 = *(float4*)&Ws[k][ty * 8];
      float4 a1 = *(float4*)&Ws[k][ty * 8 + 4];
      float4 bv = *(float4*)&xs[k][tx * 4];
      ull b01 = pack2(bv.x, bv.y), b23 = pack2(bv.z, bv.w);
      float av[8] = {a0.x, a0.y, a0.z, a0.w, a1.x, a1.y, a1.z, a1.w};
#pragma unroll
      for (int i = 0; i < 8; i++) {
        ull ad = pack2(av[i], av[i]);
        ffma2(acc[i][0], ad, b01);
        ffma2(acc[i][1], ad, b23);
      }
    }
    __syncthreads();
  }
  float* outb = &g_raw[z][b][0][0];
#pragma unroll
  for (int i = 0; i < 8; i++) {
    int o = ty * 8 + i;
    float r0, r1, r2, r3;
    unpack2(acc[i][0], r0, r1);
    unpack2(acc[i][1], r2, r3);
    *(float4*)&outb[(size_t)o * SP + s0 + tx * 4] = make_float4(r0, r1, r2, r3);
  }
}

// ============================================================
// K2: GroupNorm stats
// ============================================================
__global__ __launch_bounds__(256) void gn_stats_kernel() {
  int idx = blockIdx.x;
  int g = idx & 31, b = (idx >> 5) & 1, z = idx >> 6;
  const float* base = &g_raw[z][b][g * 4][0];
  float s = 0.f, s2 = 0.f;
  for (int i = threadIdx.x; i < 65536; i += 256) {
    float v = base[i];
    s += v; s2 = fmaf(v, v, s2);
  }
  __shared__ float sh1[256], sh2[256];
  sh1[threadIdx.x] = s; sh2[threadIdx.x] = s2;
  __syncthreads();
  for (int str = 128; str > 0; str >>= 1) {
    if (threadIdx.x < str) {
      sh1[threadIdx.x] += sh1[threadIdx.x + str];
      sh2[threadIdx.x] += sh2[threadIdx.x + str];
    }
    __syncthreads();
  }
  if (threadIdx.x == 0) {
    float mu = sh1[0] * (1.f / 65536.f);
    float var = sh2[0] * (1.f / 65536.f) - mu * mu;
    g_mu[z][b][g] = mu;
    g_rs[z][b][g] = rsqrtf(var + EPS);
  }
}

// ============================================================
// K3a: q/k normalize + pool
// ============================================================
__global__ __launch_bounds__(256) void rearrange_qk_kernel(
    const float* __restrict__ gqg, const float* __restrict__ gqb,
    const float* __restrict__ gkg, const float* __restrict__ gkb) {
  int tok = blockIdx.x * 4 + (threadIdx.x >> 6);
  int e = threadIdx.x & 63;
  int n = tok & 1023, g = (tok >> 10) & 31, b = tok >> 15;
  int d = e >> 4, p = e & 15;
  int c = g * 4 + d;
  int tt = n >> 8, hy = (n >> 4) & 15, wx = n & 15, sy = p >> 2, sx = p & 3;
  int pix = (tt * 64 + hy * 4 + sy) * 64 + wx * 4 + sx;
#pragma unroll
  for (int z = 0; z < 2; z++) {
    const float* ga = (z == 0) ? gqg : gkg;
    const float* be = (z == 0) ? gqb : gkb;
    float mu = g_mu[z][b][g], rs = g_rs[z][b][g];
    float v = (g_raw[z][b][c][pix] - mu) * rs * ga[c] + be[c];
    float r = v;
    r += __shfl_xor_sync(0xffffffffu, r, 8);
    r += __shfl_xor_sync(0xffffffffu, r, 4);
    r += __shfl_xor_sync(0xffffffffu, r, 2);
    r += __shfl_xor_sync(0xffffffffu, r, 1);
    if (p == 0) {
      if (z == 0) g_qp[b][g][n][d] = r * (1.f / 16.f);
      else        g_kp[b][g][n][d] = r * (1.f / 16.f);
    }
  }
}

// ============================================================
// K3b: V normalize -> transposed fp32 (tf32-rounded) [b][g][64][1024]
// grid (16, 32, 2): block = 64 tokens x 64 channels
// ============================================================
__global__ __launch_bounds__(256) void rearrange_v_kernel(
    const float* __restrict__ gvg, const float* __restrict__ gvb) {
  const int n0 = blockIdx.x * 64, g = blockIdx.y, b = blockIdx.z;
  const float mu = g_mu[2][b][g], rs = g_rs[2][b][g];
#pragma unroll
  for (int i = 0; i < 4; i++) {
    int idx = threadIdx.x + i * 256;  // 1024 float4 slots = 64 e x 16 n-quads
    int e = idx >> 4, nq = idx & 15;
    int n1 = n0 + nq * 4;
    int d = e >> 4, p = e & 15, c = g * 4 + d;
    float sc = rs * gvg[c], of = gvb[c] - mu * sc;
    int sy = p >> 2, sx = p & 3;
    float v[4];
#pragma unroll
    for (int q = 0; q < 4; q++) {
      int m = n1 + q;
      int pix = ((m >> 8) * 64 + ((m >> 4) & 15) * 4 + sy) * 64 + (m & 15) * 4 + sx;
      v[q] = tf32r(fmaf(g_raw[2][b][c][pix], sc, of));
    }
    *(float4*)&g_vt[b][g][e][n1] = make_float4(v[0], v[1], v[2], v[3]);
  }
}

// ============================================================
// K4: attention, PV on mma.sync tf32 (portable PTX).
// Block = (b,g,128-row tile), grid (8,32,2), 256 threads, ~81.7KB smem.
// Chunk = 64 keys: SIMT logits+exp -> tf32 P[128][68]; Vt[64][68];
// warp PV tile 32rx32c = 2 row-tiles x 4 n-tiles of m16n8k8 per kstep.
// Fragment loads are single LDS.64 via logical-k <-> physical-m remap
// (logical c <-> phys 2c / 2c+1), valid since both operands share it.
// ============================================================
__global__ __launch_bounds__(256, 2) void attn_kernel(
    const float* __restrict__ rel_table, const int* __restrict__ rel_index,
    float* __restrict__ out) {
  extern __shared__ float sm[];
  float* tab = sm;            // 6728
  float* qs  = sm + 6728;     // 512
  float* Sr  = sm + 7240;     // 128
  float* P   = sm + 7368;     // 128*68
  float* Vt  = sm + 16072;    // 64*68

  const int g = blockIdx.y, b = blockIdx.z;
  const int n0 = blockIdx.x * 128;
  const int t = threadIdx.x, lane = t & 31, w = t >> 5;
  const int grp = lane >> 2, thr = lane & 3;

  for (int i = t; i < TBL; i += 256) tab[i] = rel_table[g * TBL + i];
  if (t < 128) ((float4*)qs)[t] = ((const float4*)&g_qp[b][g][n0][0])[t];

  float acc[2][4][4];
#pragma unroll
  for (int i = 0; i < 2; i++)
#pragma unroll
    for (int j = 0; j < 4; j++)
#pragma unroll
      for (int k = 0; k < 4; k++) acc[i][j][k] = 0.f;
  float srow[8];
#pragma unroll
  for (int k = 0; k < 8; k++) srow[k] = 0.f;

  const int rbase = w * 16 + (lane >> 4) * 8;  // logits rows
  const int mq = lane & 15;                    // m-quad within chunk
  const int R0 = (w & 3) * 32;                 // PV rows
  const int N0 = (w >> 2) * 32;                // PV cols

  __syncthreads();

  for (int ch = 0; ch < 16; ch++) {
    const int m0 = ch * 64;
    if (ch) __syncthreads();  // prev mma frag reads done before overwrite

    // stage Vt chunk: 64 c x 64 m fp32 (already tf32-rounded)
#pragma unroll
    for (int i = 0; i < 4; i++) {
      int idx = t + i * 256;
      int e = idx >> 4, qd = idx & 15;
      *(float4*)&Vt[e * PSTRD + qd * 4] =
          *(const float4*)&g_vt[b][g][e][m0 + qd * 4];
    }

    // K for this lane's m-quad
    float4 kreg[4];
#pragma unroll
    for (int j = 0; j < 4; j++)
      kreg[j] = *(const float4*)&g_kp[b][g][m0 + mq * 4 + j][0];

    // logits + exp -> tf32 P (one STS.128 per row)
#pragma unroll
    for (int k = 0; k < 8; k++) {
      const int r = rbase + k;
      float4 qv = *(float4*)&qs[r * 4];
      int4 ix = *(const int4*)&rel_index[(size_t)(n0 + r) * 1024 + m0 + mq * 4];
      float e0 = tf32r(__expf(fmaf(0.5f, qv.x*kreg[0].x + qv.y*kreg[0].y + qv.z*kreg[0].z + qv.w*kreg[0].w, tab[ix.x])));
      float e1 = tf32r(__expf(fmaf(0.5f, qv.x*kreg[1].x + qv.y*kreg[1].y + qv.z*kreg[1].z + qv.w*kreg[1].w, tab[ix.y])));
      float e2 = tf32r(__expf(fmaf(0.5f, qv.x*kreg[2].x + qv.y*kreg[2].y + qv.z*kreg[2].z + qv.w*kreg[2].w, tab[ix.z])));
      float e3 = tf32r(__expf(fmaf(0.5f, qv.x*kreg[3].x + qv.y*kreg[3].y + qv.z*kreg[3].z + qv.w*kreg[3].w, tab[ix.w])));
      srow[k] += (e0 + e1) + (e2 + e3);
      *(float4*)&P[r * PSTRD + mq * 4] = make_float4(e0, e1, e2, e3);
    }
    __syncthreads();

    // PV mma: 8 ksteps of k8 (phys m = 8j..8j+7)
#pragma unroll
    for (int j = 0; j < 8; j++) {
      const int col = 8 * j + 2 * thr;
      uint2 a00 = *(uint2*)&P[(R0 + grp) * PSTRD + col];
      uint2 a01 = *(uint2*)&P[(R0 + grp + 8) * PSTRD + col];
      uint2 a10 = *(uint2*)&P[(R0 + 16 + grp) * PSTRD + col];
      uint2 a11 = *(uint2*)&P[(R0 + 24 + grp) * PSTRD + col];
#pragma unroll
      for (int nt = 0; nt < 4; nt++) {
        uint2 bb = *(uint2*)&Vt[(N0 + nt * 8 + grp) * PSTRD + col];
        mma_tf32(acc[0][nt], a00.x, a01.x, a00.y, a01.y, bb.x, bb.y);
        mma_tf32(acc[1][nt], a10.x, a11.x, a10.y, a11.y, bb.x, bb.y);
      }
    }
  }

  // row sums: reduce over 16-lane half-warps, write Sr
#pragma unroll
  for (int k = 0; k < 8; k++) {
    float s = srow[k];
    s += __shfl_xor_sync(0xffffffffu, s, 1);
    s += __shfl_xor_sync(0xffffffffu, s, 2);
    s += __shfl_xor_sync(0xffffffffu, s, 4);
    s += __shfl_xor_sync(0xffffffffu, s, 8);
    if ((lane & 15) == 0) Sr[rbase + k] = s;
  }
  __syncthreads();

  // epilogue: divide by row sums, scatter float2 (cols c, c+1)
#pragma unroll
  for (int rt = 0; rt < 2; rt++) {
    int r_lo = R0 + rt * 16 + grp, r_hi = r_lo + 8;
    float inv_lo = 1.f / Sr[r_lo], inv_hi = 1.f / Sr[r_hi];
    int nlo = n0 + r_lo, nhi = n0 + r_hi;
    size_t base_lo = ((size_t)(nlo >> 8)) * 4096 + ((nlo >> 4) & 15) * 256 + (nlo & 15) * 4;
    size_t base_hi = ((size_t)(nhi >> 8)) * 4096 + ((nhi >> 4) & 15) * 256 + (nhi & 15) * 4;
    size_t bg = ((size_t)b * 128 + g * 4) * 16384;
#pragma unroll
    for (int nt = 0; nt < 4; nt++) {
      int c = N0 + nt * 8 + 2 * thr;
      int d = c >> 4, p = c & 15, sy = p >> 2, sx = p & 3;
      size_t choff = bg + (size_t)d * 16384 + (size_t)sy * 64 + sx;
      *(float2*)&out[choff + base_lo] =
          make_float2(acc[rt][nt][0] * inv_lo, acc[rt][nt][1] * inv_lo);
      *(float2*)&out[choff + base_hi] =
          make_float2(acc[rt][nt][2] * inv_hi, acc[rt][nt][3] * inv_hi);
    }
  }
}

// ============================================================
extern "C" void kernel_launch(void* const* d_in, const int* in_sizes, int n_in,
                              void* d_out, int out_size) {
  (void)in_sizes; (void)n_in; (void)out_size;
  const float* x   = (const float*)d_in[0];
  const float* Wq  = (const float*)d_in[1];
  const float* Wk  = (const float*)d_in[2];
  const float* Wv  = (const float*)d_in[3];
  const float* gqg = (const float*)d_in[4];
  const float* gqb = (const float*)d_in[5];
  const float* gkg = (const float*)d_in[6];
  const float* gkb = (const float*)d_in[7];
  const float* gvg = (const float*)d_in[8];
  const float* gvb = (const float*)d_in[9];
  const float* rel_table = (const float*)d_in[10];
  const int*   rel_index = (const int*)d_in[11];
  float* out = (float*)d_out;

  const int smem = (16072 + 64 * PSTRD) * sizeof(float);  // 81696
  cudaFuncSetAttribute(attn_kernel, cudaFuncAttributeMaxDynamicSharedMemorySize, smem);

  proj_kernel<<<dim3(256, 2, 3), 256>>>(x, Wq, Wk, Wv);
  gn_stats_kernel<<<192, 256>>>();
  rearrange_qk_kernel<<<16384, 256>>>(gqg, gqb, gkg, gkb);
  rearrange_v_kernel<<<dim3(16, 32, 2), 256>>>(gvg, gvb);
  attn_kernel<<<dim3(8, 32, 2), 256, smem>>>(rel_table, rel_index, out);
}

// round 9
// speedup vs baseline: 1.1640x; 1.1640x over previous
#include <cuda_runtime.h>
#include <cstdint>

#define BB 2
#define NH 32
#define SP 16384   // T*H*W
#define NN 1024
#define TBL 6727   // 7*31*31
#define EPS 1e-5f
#define PSTR 68    // Pt row stride (float4-aligned, conflict-free phases)

typedef unsigned long long ull;

// ---- scratch (device globals; no allocation allowed) ----
__device__ float g_xpool[BB][128][NN];        // patch-pooled x
__device__ float g_Gpart[BB][64][128][128];   // Gram partials (8MB)
__device__ float g_G[BB][128][128];           // Gram
__device__ float g_xbar[BB][128];             // spatial mean of x
__device__ float g_Wf[3][BB][128][128];       // folded weights (GN absorbed)
__device__ float g_bf[3][BB][128];            // folded bias
__device__ float g_qp[BB][NH][NN][4];         // pooled normalized queries
__device__ float g_kp[BB][NH][NN][4];         // pooled normalized keys
__device__ float g_vp[BB][NH][NN][64];        // normalized values [n][e]

__device__ __forceinline__ void ffma2(ull& d, ull a, ull b) {
  asm("fma.rn.f32x2 %0, %1, %2, %0;" : "+l"(d) : "l"(a), "l"(b));
}
__device__ __forceinline__ ull pack2(float lo, float hi) {
  ull r; asm("mov.b64 %0, {%1, %2};" : "=l"(r) : "f"(lo), "f"(hi)); return r;
}
__device__ __forceinline__ void unpack2(ull v, float& lo, float& hi) {
  asm("mov.b64 {%0, %1}, %2;" : "=f"(lo), "=f"(hi) : "l"(v));
}

// ============================================================
// K1: patch-pool x -> g_xpool[b][c][n]  (mean over 16 pixels)
// grid (128, 2), 256 threads
// ============================================================
__global__ __launch_bounds__(256) void pool_x_kernel(const float* __restrict__ x) {
  const int c = blockIdx.x, b = blockIdx.y;
  const float* xp = x + ((size_t)b * 128 + c) * SP;
#pragma unroll
  for (int it = 0; it < 4; it++) {
    int n = threadIdx.x + it * 256;
    int tt = n >> 8, hy = (n >> 4) & 15, wx = n & 15;
    const float* base = xp + (tt * 64 + hy * 4) * 64 + wx * 4;
    float s = 0.f;
#pragma unroll
    for (int sy = 0; sy < 4; sy++) {
      float4 v = *(const float4*)(base + sy * 64);
      s += (v.x + v.y) + (v.z + v.w);
    }
    g_xpool[b][c][n] = s * (1.f / 16.f);
  }
}

// ============================================================
// K2: Gram partials  G_part = X_chunk X_chunk^T (chunk = 256 s)
// grid (64, 2), 256 threads; thread = 8x8 tile of the 128x128 output
// ============================================================
__global__ __launch_bounds__(256) void gram_kernel(const float* __restrict__ x) {
  const int b = blockIdx.y;
  const int s0 = blockIdx.x * 256;
  __shared__ float xsm[16][132];
  const int t = threadIdx.x, tx = t & 15, ty = t >> 4;
  ull acc[8][4];
#pragma unroll
  for (int i = 0; i < 8; i++)
#pragma unroll
    for (int j = 0; j < 4; j++) acc[i][j] = 0ull;
  const float* xb = x + (size_t)b * 128 * SP;
  for (int ks = 0; ks < 16; ks++) {
#pragma unroll
    for (int i = 0; i < 2; i++) {
      int idx = t + i * 256;
      int c = idx >> 2, sq = idx & 3;
      float4 v = *(const float4*)&xb[(size_t)c * SP + s0 + ks * 16 + sq * 4];
      xsm[sq * 4 + 0][c] = v.x; xsm[sq * 4 + 1][c] = v.y;
      xsm[sq * 4 + 2][c] = v.z; xsm[sq * 4 + 3][c] = v.w;
    }
    __syncthreads();
#pragma unroll
    for (int k = 0; k < 16; k++) {
      float4 a0 = *(float4*)&xsm[k][ty * 8];
      float4 a1 = *(float4*)&xsm[k][ty * 8 + 4];
      float4 b0 = *(float4*)&xsm[k][tx * 8];
      float4 b1 = *(float4*)&xsm[k][tx * 8 + 4];
      ull p01 = pack2(b0.x, b0.y), p23 = pack2(b0.z, b0.w);
      ull p45 = pack2(b1.x, b1.y), p67 = pack2(b1.z, b1.w);
      float av[8] = {a0.x, a0.y, a0.z, a0.w, a1.x, a1.y, a1.z, a1.w};
#pragma unroll
      for (int i = 0; i < 8; i++) {
        ull ad = pack2(av[i], av[i]);
        ffma2(acc[i][0], ad, p01); ffma2(acc[i][1], ad, p23);
        ffma2(acc[i][2], ad, p45); ffma2(acc[i][3], ad, p67);
      }
    }
    __syncthreads();
  }
  float* gp = &g_Gpart[b][blockIdx.x][0][0];
#pragma unroll
  for (int i = 0; i < 8; i++) {
    int row = ty * 8 + i;
    float r0, r1, r2, r3, r4, r5, r6, r7;
    unpack2(acc[i][0], r0, r1); unpack2(acc[i][1], r2, r3);
    unpack2(acc[i][2], r4, r5); unpack2(acc[i][3], r6, r7);
    *(float4*)&gp[row * 128 + tx * 8]     = make_float4(r0, r1, r2, r3);
    *(float4*)&gp[row * 128 + tx * 8 + 4] = make_float4(r4, r5, r6, r7);
  }
}

// ============================================================
// K3: reduce Gram partials + xbar.  grid (128, 2), 128 threads
// ============================================================
__global__ __launch_bounds__(128) void gram_reduce_kernel() {
  const int c = blockIdx.x, b = blockIdx.y;
  const int t = threadIdx.x;
  float s = 0.f;
  for (int p = 0; p < 64; p++) s += g_Gpart[b][p][c][t];
  g_G[b][c][t] = s;
  // xbar via xpool (mean over n of patch means == spatial mean)
  float xs = 0.f;
#pragma unroll
  for (int i = 0; i < 8; i++) xs += g_xpool[b][c][t + i * 128];
  __shared__ float red[128];
  red[t] = xs;
  __syncthreads();
  for (int str = 64; str > 0; str >>= 1) {
    if (t < str) red[t] += red[t + str];
    __syncthreads();
  }
  if (t == 0) g_xbar[b][c] = red[0] * (1.f / 1024.f);
}

// ============================================================
// K4: fold GN stats into weights.
// grid (16 c-octets, 3 z, 2 b), 256 threads.
// mu_g = 1/4 sum_{c in g} W_c . xbar;  E[y^2]_g = sum W_c^T G W_c/(4*SP)
// ============================================================
__global__ __launch_bounds__(256) void fold_kernel(
    const float* __restrict__ Wq, const float* __restrict__ Wk,
    const float* __restrict__ Wv,
    const float* __restrict__ gqg, const float* __restrict__ gqb,
    const float* __restrict__ gkg, const float* __restrict__ gkb,
    const float* __restrict__ gvg, const float* __restrict__ gvb) {
  const int coct = blockIdx.x, z = blockIdx.y, b = blockIdx.z;
  const int t = threadIdx.x;
  const float* Wm = (z == 0) ? Wq : (z == 1 ? Wk : Wv);
  const float* ga = (z == 0) ? gqg : (z == 1 ? gkg : gvg);
  const float* be = (z == 0) ? gqb : (z == 1 ? gkb : gvb);
  __shared__ float Wc[8][128];
  __shared__ float sx[128];
  __shared__ float s_s[8], s_m[8];
  __shared__ float red1[256], red2[256];
  __shared__ float muv[2], rsv[2];
#pragma unroll
  for (int i = 0; i < 4; i++) {
    int idx = t + i * 256;
    Wc[idx >> 7][idx & 127] = Wm[(coct * 8 + (idx >> 7)) * 128 + (idx & 127)];
  }
  if (t < 128) sx[t] = g_xbar[b][t];
  __syncthreads();

  const int j = t >> 1, khalf = (t & 1) * 64;
  for (int c8 = 0; c8 < 8; c8++) {
    const float* Gj = &g_G[b][j][khalf];
    const float* Wk8 = &Wc[c8][khalf];
    float dot = 0.f;
#pragma unroll
    for (int kk = 0; kk < 16; kk++) {
      float4 gv = *(const float4*)&Gj[kk * 4];
      float4 wv = *(const float4*)&Wk8[kk * 4];
      dot += gv.x * wv.x + gv.y * wv.y + gv.z * wv.z + gv.w * wv.w;
    }
    red1[t] = Wc[c8][j] * dot;
    red2[t] = (t < 128) ? Wc[c8][t] * sx[t] : 0.f;
    __syncthreads();
    for (int str = 128; str > 0; str >>= 1) {
      if (t < str) { red1[t] += red1[t + str]; red2[t] += red2[t + str]; }
      __syncthreads();
    }
    if (t == 0) { s_s[c8] = red1[0]; s_m[c8] = red2[0]; }
    __syncthreads();
  }
  if (t < 2) {
    float m = 0.25f * (s_m[t * 4] + s_m[t * 4 + 1] + s_m[t * 4 + 2] + s_m[t * 4 + 3]);
    float e2 = (s_s[t * 4] + s_s[t * 4 + 1] + s_s[t * 4 + 2] + s_s[t * 4 + 3]) *
               (1.f / (4.f * (float)SP));
    float var = e2 - m * m;
    muv[t] = m;
    rsv[t] = rsqrtf(var + EPS);
  }
  __syncthreads();
#pragma unroll
  for (int i = 0; i < 4; i++) {
    int idx = t + i * 256;
    int row = idx >> 7, k = idx & 127;
    int c = coct * 8 + row, gg = row >> 2;
    g_Wf[z][b][c][k] = rsv[gg] * ga[c] * Wc[row][k];
  }
  if (t < 8) {
    int c = coct * 8 + t, gg = t >> 2;
    g_bf[z][b][c] = be[c] - muv[gg] * rsv[gg] * ga[c];
  }
}

// ============================================================
// K5: pooled q/k GEMM: [128 oc x 64 n] = Wf[z] @ xpool + bf
// grid (16 n-tiles, 2 z, 2 b), 256 threads
// ============================================================
__global__ __launch_bounds__(256) void qk_gemm_kernel() {
  const int z = blockIdx.y, b = blockIdx.z;
  const int n0 = blockIdx.x * 64;
  const float* Wm = &g_Wf[z][b][0][0];
  __shared__ float Ws[16][128];
  __shared__ float xs[16][64];
  const int t = threadIdx.x, tx = t & 15, ty = t >> 4;
  float acc[8][4];
#pragma unroll
  for (int i = 0; i < 8; i++) { acc[i][0]=0.f; acc[i][1]=0.f; acc[i][2]=0.f; acc[i][3]=0.f; }
  for (int kc = 0; kc < 128; kc += 16) {
    {
      int o = t >> 1, koff = (t & 1) * 8;
      const float* wp = Wm + o * 128 + kc + koff;
      float4 w0 = *(const float4*)wp;
      float4 w1 = *(const float4*)(wp + 4);
      Ws[koff + 0][o] = w0.x; Ws[koff + 1][o] = w0.y;
      Ws[koff + 2][o] = w0.z; Ws[koff + 3][o] = w0.w;
      Ws[koff + 4][o] = w1.x; Ws[koff + 5][o] = w1.y;
      Ws[koff + 6][o] = w1.z; Ws[koff + 7][o] = w1.w;
    }
    *(float4*)&xs[ty][tx * 4] = *(const float4*)&g_xpool[b][kc + ty][n0 + tx * 4];
    __syncthreads();
#pragma unroll
    for (int k = 0; k < 16; k++) {
      float4 a0 = *(float4*)&Ws[k][ty * 8];
      float4 a1 = *(float4*)&Ws[k][ty * 8 + 4];
      float4 bv = *(float4*)&xs[k][tx * 4];
      float av[8] = {a0.x, a0.y, a0.z, a0.w, a1.x, a1.y, a1.z, a1.w};
#pragma unroll
      for (int i = 0; i < 8; i++) {
        acc[i][0] = fmaf(av[i], bv.x, acc[i][0]);
        acc[i][1] = fmaf(av[i], bv.y, acc[i][1]);
        acc[i][2] = fmaf(av[i], bv.z, acc[i][2]);
        acc[i][3] = fmaf(av[i], bv.w, acc[i][3]);
      }
    }
    __syncthreads();
  }
#pragma unroll
  for (int i = 0; i < 8; i++) {
    int c = ty * 8 + i, g = c >> 2, d = c & 3;
    float bias = g_bf[z][b][c];
    float* dst = (z == 0) ? &g_qp[b][g][0][0] : &g_kp[b][g][0][0];
#pragma unroll
    for (int jj = 0; jj < 4; jj++)
      dst[(n0 + tx * 4 + jj) * 4 + d] = acc[i][jj] + bias;
  }
}

// ============================================================
// K6: V GEMM full-res: [128 oc x 64 s] tile -> g_vp[b][g][n][e]
// grid (256 s-tiles, 2 b), 256 threads
// ============================================================
__global__ __launch_bounds__(256) void v_gemm_kernel(const float* __restrict__ x) {
  const int b = blockIdx.y;
  const int s0 = blockIdx.x * 64;
  const float* Wm = &g_Wf[2][b][0][0];
  __shared__ float Ws[16][128];
  __shared__ float xs[16][64];
  const int t = threadIdx.x, tx = t & 15, ty = t >> 4;
  ull acc[8][2];
#pragma unroll
  for (int i = 0; i < 8; i++) { acc[i][0] = 0ull; acc[i][1] = 0ull; }
  const float* xb = x + (size_t)b * 128 * SP;
  for (int kc = 0; kc < 128; kc += 16) {
    {
      int o = t >> 1, koff = (t & 1) * 8;
      const float* wp = Wm + o * 128 + kc + koff;
      float4 w0 = *(const float4*)wp;
      float4 w1 = *(const float4*)(wp + 4);
      Ws[koff + 0][o] = w0.x; Ws[koff + 1][o] = w0.y;
      Ws[koff + 2][o] = w0.z; Ws[koff + 3][o] = w0.w;
      Ws[koff + 4][o] = w1.x; Ws[koff + 5][o] = w1.y;
      Ws[koff + 6][o] = w1.z; Ws[koff + 7][o] = w1.w;
    }
    *(float4*)&xs[ty][tx * 4] = *(const float4*)&xb[(size_t)(kc + ty) * SP + s0 + tx * 4];
    __syncthreads();
#pragma unroll
    for (int k = 0; k < 16; k++) {
      float4 a0 = *(float4*)&Ws[k][ty * 8];
      float4 a1 = *(float4*)&Ws[k][ty * 8 + 4];
      float4 bv = *(float4*)&xs[k][tx * 4];
      ull b01 = pack2(bv.x, bv.y), b23 = pack2(bv.z, bv.w);
      float av[8] = {a0.x, a0.y, a0.z, a0.w, a1.x, a1.y, a1.z, a1.w};
#pragma unroll
      for (int i = 0; i < 8; i++) {
        ull ad = pack2(av[i], av[i]);
        ffma2(acc[i][0], ad, b01);
        ffma2(acc[i][1], ad, b23);
      }
    }
    __syncthreads();
  }
  // epilogue: s-tile = one w-row: row = blockIdx.x
  const int row = blockIdx.x;
  const int tt = row >> 6, hrow = row & 63, hy = hrow >> 2, sy = hrow & 3;
  const int n = (tt * 16 + hy) * 16 + tx;
#pragma unroll
  for (int i = 0; i < 8; i++) {
    int c = ty * 8 + i, g = c >> 2, d = c & 3;
    float bias = g_bf[2][b][c];
    float r0, r1, r2, r3;
    unpack2(acc[i][0], r0, r1);
    unpack2(acc[i][1], r2, r3);
    *(float4*)&g_vp[b][g][n][d * 16 + sy * 4] =
        make_float4(r0 + bias, r1 + bias, r2 + bias, r3 + bias);
  }
}

// ============================================================
// K7: fused attention (R4, 363.5us version - proven).
// ============================================================
__global__ __launch_bounds__(256, 2) void attn_kernel(
    const float* __restrict__ rel_table, const int* __restrict__ rel_index,
    float* __restrict__ out) {
  extern __shared__ float sm[];
  float* tab = sm;                 // 6728
  float* qs  = tab + 6728;         // 256    [r*4+d]
  float* vs  = qs + 256;           // 8192   [m*64+e]
  float* Pt  = vs + 8192;          // 128*PSTR [m][r] transposed
  float* Sr  = Pt + 128 * PSTR;    // 64 row sums

  const int tile = blockIdx.x, g = blockIdx.y, b = blockIdx.z;
  const int n0 = tile * 64;
  const int t = threadIdx.x;
  const int lane = t & 31, w = t >> 5;

  for (int i = t; i < TBL; i += 256) tab[i] = rel_table[g * TBL + i];
  qs[t] = g_qp[b][g][n0 + (t >> 2)][t & 3];

  ull acc[4][2];
#pragma unroll
  for (int i = 0; i < 4; i++) { acc[i][0] = 0ull; acc[i][1] = 0ull; }
  float srow[8];
#pragma unroll
  for (int k = 0; k < 8; k++) srow[k] = 0.f;

  const int rbase = w * 8;                         // logits rows
  const int rpv = (w & 1) * 32 + (lane & 7) * 4;   // PV rows
  const int cpv = (w >> 1) * 16 + (lane >> 3) * 4; // PV cols

  __syncthreads();

  for (int ch = 0; ch < 8; ch++) {
    const int m0 = ch * 128;
    if (ch) __syncthreads();

    const float4* vsrc = (const float4*)&g_vp[b][g][m0][0];
#pragma unroll
    for (int i = 0; i < 8; i++)
      ((float4*)vs)[t + i * 256] = vsrc[t + i * 256];

#pragma unroll
    for (int j = 0; j < 4; j++) {
      const int m = lane + 32 * j;
      float4 kv = *(const float4*)&g_kp[b][g][m0 + m][0];
      const int* ip = &rel_index[(size_t)(n0 + rbase) * 1024 + m0 + m];
      float e_buf[8];
#pragma unroll
      for (int k = 0; k < 8; k++) {
        float4 qv = *(float4*)&qs[(rbase + k) * 4];
        float l = 0.5f * (qv.x * kv.x + qv.y * kv.y + qv.z * kv.z + qv.w * kv.w)
                  + tab[ip[(size_t)k * 1024]];
        float e = __expf(l);
        e_buf[k] = e;
        srow[k] += e;
      }
      *(float4*)&Pt[m * PSTR + rbase]     = make_float4(e_buf[0], e_buf[1], e_buf[2], e_buf[3]);
      *(float4*)&Pt[m * PSTR + rbase + 4] = make_float4(e_buf[4], e_buf[5], e_buf[6], e_buf[7]);
    }
    __syncthreads();

#pragma unroll 4
    for (int m = 0; m < 128; m++) {
      float4 pr = *(float4*)&Pt[m * PSTR + rpv];
      float4 vv = *(float4*)&vs[m * 64 + cpv];
      ull v01 = pack2(vv.x, vv.y), v23 = pack2(vv.z, vv.w);
      ull p0 = pack2(pr.x, pr.x), p1 = pack2(pr.y, pr.y);
      ull p2 = pack2(pr.z, pr.z), p3 = pack2(pr.w, pr.w);
      ffma2(acc[0][0], p0, v01); ffma2(acc[0][1], p0, v23);
      ffma2(acc[1][0], p1, v01); ffma2(acc[1][1], p1, v23);
      ffma2(acc[2][0], p2, v01); ffma2(acc[2][1], p2, v23);
      ffma2(acc[3][0], p3, v01); ffma2(acc[3][1], p3, v23);
    }
  }

#pragma unroll
  for (int k = 0; k < 8; k++) {
    float s = srow[k];
    s += __shfl_xor_sync(0xffffffffu, s, 16);
    s += __shfl_xor_sync(0xffffffffu, s, 8);
    s += __shfl_xor_sync(0xffffffffu, s, 4);
    s += __shfl_xor_sync(0xffffffffu, s, 2);
    s += __shfl_xor_sync(0xffffffffu, s, 1);
    if (lane == 0) Sr[rbase + k] = s;
  }
  __syncthreads();

  const int d = w >> 1, sy = lane >> 3;
#pragma unroll
  for (int i = 0; i < 4; i++) {
    int r = rpv + i;
    float inv = 1.f / Sr[r];
    float a0, a1, a2, a3;
    unpack2(acc[i][0], a0, a1);
    unpack2(acc[i][1], a2, a3);
    int n = n0 + r;
    int tt = n >> 8, hy = (n >> 4) & 15, wx = n & 15;
    size_t off = ((((size_t)b * 128 + g * 4 + d) * 4 + tt) * 64 + hy * 4 + sy) * 64 + wx * 4;
    *(float4*)&out[off] = make_float4(a0 * inv, a1 * inv, a2 * inv, a3 * inv);
  }
}

// ============================================================
extern "C" void kernel_launch(void* const* d_in, const int* in_sizes, int n_in,
                              void* d_out, int out_size) {
  (void)in_sizes; (void)n_in; (void)out_size;
  const float* x   = (const float*)d_in[0];
  const float* Wq  = (const float*)d_in[1];
  const float* Wk  = (const float*)d_in[2];
  const float* Wv  = (const float*)d_in[3];
  const float* gqg = (const float*)d_in[4];
  const float* gqb = (const float*)d_in[5];
  const float* gkg = (const float*)d_in[6];
  const float* gkb = (const float*)d_in[7];
  const float* gvg = (const float*)d_in[8];
  const float* gvb = (const float*)d_in[9];
  const float* rel_table = (const float*)d_in[10];
  const int*   rel_index = (const int*)d_in[11];
  float* out = (float*)d_out;

  const int smem = (6728 + 256 + 8192 + 128 * PSTR + 64) * sizeof(float);  // 95776
  cudaFuncSetAttribute(attn_kernel, cudaFuncAttributeMaxDynamicSharedMemorySize, smem);

  pool_x_kernel<<<dim3(128, 2), 256>>>(x);
  gram_kernel<<<dim3(64, 2), 256>>>(x);
  gram_reduce_kernel<<<dim3(128, 2), 128>>>();
  fold_kernel<<<dim3(16, 3, 2), 256>>>(Wq, Wk, Wv, gqg, gqb, gkg, gkb, gvg, gvb);
  qk_gemm_kernel<<<dim3(16, 2, 2), 256>>>();
  v_gemm_kernel<<<dim3(256, 2), 256>>>(x);
  attn_kernel<<<dim3(16, 32, 2), 256, smem>>>(rel_table, rel_index, out);
}

// round 12
// speedup vs baseline: 1.2217x; 1.0496x over previous
#include <cuda_runtime.h>
#include <cstdint>

#define BB 2
#define NH 32
#define SP 16384   // T*H*W
#define NN 1024
#define TBL 6727   // 7*31*31
#define EPS 1e-5f
#define PSTR 68    // Pt row stride (float4-aligned, conflict-free phases)
#define RELC 3363  // 3*961 + 15*31 + 15

typedef unsigned long long ull;

// ---- scratch (device globals; no allocation allowed) ----
__device__ float g_xpool[BB][128][NN];        // patch-pooled x
__device__ float g_Gpart[BB][64][128][128];   // Gram partials (8MB)
__device__ float g_G[BB][128][128];           // Gram
__device__ float g_xbar[BB][128];             // spatial mean of x
__device__ float g_Wf[3][BB][128][128];       // folded weights (GN absorbed)
__device__ float g_bf[3][BB][128];            // folded bias
__device__ float g_qp[BB][NH][NN][4];         // pooled normalized queries
__device__ float g_kp[BB][NH][NN][4];         // pooled normalized keys
__device__ float g_vp[BB][NH][NN][64];        // normalized values [n][e]

__device__ __forceinline__ void ffma2(ull& d, ull a, ull b) {
  asm("fma.rn.f32x2 %0, %1, %2, %0;" : "+l"(d) : "l"(a), "l"(b));
}
__device__ __forceinline__ ull pack2(float lo, float hi) {
  ull r; asm("mov.b64 %0, {%1, %2};" : "=l"(r) : "f"(lo), "f"(hi)); return r;
}
__device__ __forceinline__ void unpack2(ull v, float& lo, float& hi) {
  asm("mov.b64 {%0, %1}, %2;" : "=f"(lo), "=f"(hi) : "l"(v));
}
// a(n) for the affine rel-position index: idx(r,m) = a(r) - a(m) + RELC
__device__ __forceinline__ int rel_a(int n) {
  return (n >> 8) * 961 + ((n >> 4) & 15) * 31 + (n & 15);
}

// ============================================================
// K1: patch-pool x -> g_xpool[b][c][n]
// ============================================================
__global__ __launch_bounds__(256) void pool_x_kernel(const float* __restrict__ x) {
  const int c = blockIdx.x, b = blockIdx.y;
  const float* xp = x + ((size_t)b * 128 + c) * SP;
#pragma unroll
  for (int it = 0; it < 4; it++) {
    int n = threadIdx.x + it * 256;
    int tt = n >> 8, hy = (n >> 4) & 15, wx = n & 15;
    const float* base = xp + (tt * 64 + hy * 4) * 64 + wx * 4;
    float s = 0.f;
#pragma unroll
    for (int sy = 0; sy < 4; sy++) {
      float4 v = *(const float4*)(base + sy * 64);
      s += (v.x + v.y) + (v.z + v.w);
    }
    g_xpool[b][c][n] = s * (1.f / 16.f);
  }
}

// ============================================================
// K2: Gram partials
// ============================================================
__global__ __launch_bounds__(256) void gram_kernel(const float* __restrict__ x) {
  const int b = blockIdx.y;
  const int s0 = blockIdx.x * 256;
  __shared__ float xsm[16][132];
  const int t = threadIdx.x, tx = t & 15, ty = t >> 4;
  ull acc[8][4];
#pragma unroll
  for (int i = 0; i < 8; i++)
#pragma unroll
    for (int j = 0; j < 4; j++) acc[i][j] = 0ull;
  const float* xb = x + (size_t)b * 128 * SP;
  for (int ks = 0; ks < 16; ks++) {
#pragma unroll
    for (int i = 0; i < 2; i++) {
      int idx = t + i * 256;
      int c = idx >> 2, sq = idx & 3;
      float4 v = *(const float4*)&xb[(size_t)c * SP + s0 + ks * 16 + sq * 4];
      xsm[sq * 4 + 0][c] = v.x; xsm[sq * 4 + 1][c] = v.y;
      xsm[sq * 4 + 2][c] = v.z; xsm[sq * 4 + 3][c] = v.w;
    }
    __syncthreads();
#pragma unroll
    for (int k = 0; k < 16; k++) {
      float4 a0 = *(float4*)&xsm[k][ty * 8];
      float4 a1 = *(float4*)&xsm[k][ty * 8 + 4];
      float4 b0 = *(float4*)&xsm[k][tx * 8];
      float4 b1 = *(float4*)&xsm[k][tx * 8 + 4];
      ull p01 = pack2(b0.x, b0.y), p23 = pack2(b0.z, b0.w);
      ull p45 = pack2(b1.x, b1.y), p67 = pack2(b1.z, b1.w);
      float av[8] = {a0.x, a0.y, a0.z, a0.w, a1.x, a1.y, a1.z, a1.w};
#pragma unroll
      for (int i = 0; i < 8; i++) {
        ull ad = pack2(av[i], av[i]);
        ffma2(acc[i][0], ad, p01); ffma2(acc[i][1], ad, p23);
        ffma2(acc[i][2], ad, p45); ffma2(acc[i][3], ad, p67);
      }
    }
    __syncthreads();
  }
  float* gp = &g_Gpart[b][blockIdx.x][0][0];
#pragma unroll
  for (int i = 0; i < 8; i++) {
    int row = ty * 8 + i;
    float r0, r1, r2, r3, r4, r5, r6, r7;
    unpack2(acc[i][0], r0, r1); unpack2(acc[i][1], r2, r3);
    unpack2(acc[i][2], r4, r5); unpack2(acc[i][3], r6, r7);
    *(float4*)&gp[row * 128 + tx * 8]     = make_float4(r0, r1, r2, r3);
    *(float4*)&gp[row * 128 + tx * 8 + 4] = make_float4(r4, r5, r6, r7);
  }
}

// ============================================================
// K3: reduce Gram partials + xbar
// ============================================================
__global__ __launch_bounds__(128) void gram_reduce_kernel() {
  const int c = blockIdx.x, b = blockIdx.y;
  const int t = threadIdx.x;
  float s = 0.f;
  for (int p = 0; p < 64; p++) s += g_Gpart[b][p][c][t];
  g_G[b][c][t] = s;
  float xs = 0.f;
#pragma unroll
  for (int i = 0; i < 8; i++) xs += g_xpool[b][c][t + i * 128];
  __shared__ float red[128];
  red[t] = xs;
  __syncthreads();
  for (int str = 64; str > 0; str >>= 1) {
    if (t < str) red[t] += red[t + str];
    __syncthreads();
  }
  if (t == 0) g_xbar[b][c] = red[0] * (1.f / 1024.f);
}

// ============================================================
// K4: fold GN stats into weights. v2: warp-per-channel, no tree reductions.
// grid (16 c-octets, 3 z, 2 b), 256 threads = 8 warps = 8 channels.
// Quadratic form per warp: lanes own k-columns (coalesced G rows).
// ============================================================
__global__ __launch_bounds__(256) void fold_kernel(
    const float* __restrict__ Wq, const float* __restrict__ Wk,
    const float* __restrict__ Wv,
    const float* __restrict__ gqg, const float* __restrict__ gqb,
    const float* __restrict__ gkg, const float* __restrict__ gkb,
    const float* __restrict__ gvg, const float* __restrict__ gvb) {
  const int coct = blockIdx.x, z = blockIdx.y, b = blockIdx.z;
  const int t = threadIdx.x, lane = t & 31, w = t >> 5;
  const float* Wm = (z == 0) ? Wq : (z == 1 ? Wk : Wv);
  const float* ga = (z == 0) ? gqg : (z == 1 ? gkg : gvg);
  const float* be = (z == 0) ? gqb : (z == 1 ? gkb : gvb);
  __shared__ float Wc[8][128];
  __shared__ float s_s[8], s_m[8];
  __shared__ float muv[2], rsv[2];
#pragma unroll
  for (int i = 0; i < 4; i++) {
    int idx = t + i * 256;
    Wc[idx >> 7][idx & 127] = Wm[(coct * 8 + (idx >> 7)) * 128 + (idx & 127)];
  }
  __syncthreads();

  // warp w handles channel c = coct*8 + w
  float wl[4], sxl[4];
#pragma unroll
  for (int i = 0; i < 4; i++) {
    wl[i] = Wc[w][lane + 32 * i];
    sxl[i] = g_xbar[b][lane + 32 * i];
  }
  float m = wl[0] * sxl[0] + wl[1] * sxl[1] + wl[2] * sxl[2] + wl[3] * sxl[3];
  float s = 0.f;
  const float* Gb = &g_G[b][0][0];
#pragma unroll 4
  for (int j = 0; j < 128; j++) {
    float wj = Wc[w][j];                       // smem broadcast
    const float* Gj = Gb + j * 128;
    float d = wl[0] * Gj[lane] + wl[1] * Gj[lane + 32] +
              wl[2] * Gj[lane + 64] + wl[3] * Gj[lane + 96];
    s = fmaf(wj, d, s);
  }
#pragma unroll
  for (int o = 16; o > 0; o >>= 1) {
    s += __shfl_xor_sync(0xffffffffu, s, o);
    m += __shfl_xor_sync(0xffffffffu, m, o);
  }
  if (lane == 0) { s_s[w] = s; s_m[w] = m; }
  __syncthreads();
  if (t < 2) {
    float mm = 0.25f * (s_m[t * 4] + s_m[t * 4 + 1] + s_m[t * 4 + 2] + s_m[t * 4 + 3]);
    float e2 = (s_s[t * 4] + s_s[t * 4 + 1] + s_s[t * 4 + 2] + s_s[t * 4 + 3]) *
               (1.f / (4.f * (float)SP));
    muv[t] = mm;
    rsv[t] = rsqrtf(e2 - mm * mm + EPS);
  }
  __syncthreads();
#pragma unroll
  for (int i = 0; i < 4; i++) {
    int idx = t + i * 256;
    int row = idx >> 7, k = idx & 127;
    int c = coct * 8 + row, lg = row >> 2;
    g_Wf[z][b][c][k] = rsv[lg] * ga[c] * Wc[row][k];
  }
  if (t < 8) {
    int c = coct * 8 + t, lg = t >> 2;
    g_bf[z][b][c] = be[c] - muv[lg] * rsv[lg] * ga[c];
  }
}

// ============================================================
// K5: pooled q/k GEMM
// ============================================================
__global__ __launch_bounds__(256) void qk_gemm_kernel() {
  const int z = blockIdx.y, b = blockIdx.z;
  const int n0 = blockIdx.x * 64;
  const float* Wm = &g_Wf[z][b][0][0];
  __shared__ float Ws[16][128];
  __shared__ float xs[16][64];
  const int t = threadIdx.x, tx = t & 15, ty = t >> 4;
  float acc[8][4];
#pragma unroll
  for (int i = 0; i < 8; i++) { acc[i][0]=0.f; acc[i][1]=0.f; acc[i][2]=0.f; acc[i][3]=0.f; }
  for (int kc = 0; kc < 128; kc += 16) {
    {
      int o = t >> 1, koff = (t & 1) * 8;
      const float* wp = Wm + o * 128 + kc + koff;
      float4 w0 = *(const float4*)wp;
      float4 w1 = *(const float4*)(wp + 4);
      Ws[koff + 0][o] = w0.x; Ws[koff + 1][o] = w0.y;
      Ws[koff + 2][o] = w0.z; Ws[koff + 3][o] = w0.w;
      Ws[koff + 4][o] = w1.x; Ws[koff + 5][o] = w1.y;
      Ws[koff + 6][o] = w1.z; Ws[koff + 7][o] = w1.w;
    }
    *(float4*)&xs[ty][tx * 4] = *(const float4*)&g_xpool[b][kc + ty][n0 + tx * 4];
    __syncthreads();
#pragma unroll
    for (int k = 0; k < 16; k++) {
      float4 a0 = *(float4*)&Ws[k][ty * 8];
      float4 a1 = *(float4*)&Ws[k][ty * 8 + 4];
      float4 bv = *(float4*)&xs[k][tx * 4];
      float av[8] = {a0.x, a0.y, a0.z, a0.w, a1.x, a1.y, a1.z, a1.w};
#pragma unroll
      for (int i = 0; i < 8; i++) {
        acc[i][0] = fmaf(av[i], bv.x, acc[i][0]);
        acc[i][1] = fmaf(av[i], bv.y, acc[i][1]);
        acc[i][2] = fmaf(av[i], bv.z, acc[i][2]);
        acc[i][3] = fmaf(av[i], bv.w, acc[i][3]);
      }
    }
    __syncthreads();
  }
#pragma unroll
  for (int i = 0; i < 8; i++) {
    int c = ty * 8 + i, g = c >> 2, d = c & 3;
    float bias = g_bf[z][b][c];
    float* dst = (z == 0) ? &g_qp[b][g][0][0] : &g_kp[b][g][0][0];
#pragma unroll
    for (int jj = 0; jj < 4; jj++)
      dst[(n0 + tx * 4 + jj) * 4 + d] = acc[i][jj] + bias;
  }
}

// ============================================================
// K6: V GEMM full-res
// ============================================================
__global__ __launch_bounds__(256) void v_gemm_kernel(const float* __restrict__ x) {
  const int b = blockIdx.y;
  const int s0 = blockIdx.x * 64;
  const float* Wm = &g_Wf[2][b][0][0];
  __shared__ float Ws[16][128];
  __shared__ float xs[16][64];
  const int t = threadIdx.x, tx = t & 15, ty = t >> 4;
  ull acc[8][2];
#pragma unroll
  for (int i = 0; i < 8; i++) { acc[i][0] = 0ull; acc[i][1] = 0ull; }
  const float* xb = x + (size_t)b * 128 * SP;
  for (int kc = 0; kc < 128; kc += 16) {
    {
      int o = t >> 1, koff = (t & 1) * 8;
      const float* wp = Wm + o * 128 + kc + koff;
      float4 w0 = *(const float4*)wp;
      float4 w1 = *(const float4*)(wp + 4);
      Ws[koff + 0][o] = w0.x; Ws[koff + 1][o] = w0.y;
      Ws[koff + 2][o] = w0.z; Ws[koff + 3][o] = w0.w;
      Ws[koff + 4][o] = w1.x; Ws[koff + 5][o] = w1.y;
      Ws[koff + 6][o] = w1.z; Ws[koff + 7][o] = w1.w;
    }
    *(float4*)&xs[ty][tx * 4] = *(const float4*)&xb[(size_t)(kc + ty) * SP + s0 + tx * 4];
    __syncthreads();
#pragma unroll
    for (int k = 0; k < 16; k++) {
      float4 a0 = *(float4*)&Ws[k][ty * 8];
      float4 a1 = *(float4*)&Ws[k][ty * 8 + 4];
      float4 bv = *(float4*)&xs[k][tx * 4];
      ull b01 = pack2(bv.x, bv.y), b23 = pack2(bv.z, bv.w);
      float av[8] = {a0.x, a0.y, a0.z, a0.w, a1.x, a1.y, a1.z, a1.w};
#pragma unroll
      for (int i = 0; i < 8; i++) {
        ull ad = pack2(av[i], av[i]);
        ffma2(acc[i][0], ad, b01);
        ffma2(acc[i][1], ad, b23);
      }
    }
    __syncthreads();
  }
  const int row = blockIdx.x;
  const int tt = row >> 6, hrow = row & 63, hy = hrow >> 2, sy = hrow & 3;
  const int n = (tt * 16 + hy) * 16 + tx;
#pragma unroll
  for (int i = 0; i < 8; i++) {
    int c = ty * 8 + i, g = c >> 2, d = c & 3;
    float bias = g_bf[2][b][c];
    float r0, r1, r2, r3;
    unpack2(acc[i][0], r0, r1);
    unpack2(acc[i][1], r2, r3);
    *(float4*)&g_vp[b][g][n][d * 16 + sy * 4] =
        make_float4(r0 + bias, r1 + bias, r2 + bias, r3 + bias);
  }
}

// ============================================================
// K7: fused attention. R4-proven structure, but rel_index computed
// arithmetically: idx(r,m) = a(r) - a(m) + RELC  (zero LDG traffic).
// ============================================================
__global__ __launch_bounds__(256, 2) void attn_kernel(
    const float* __restrict__ rel_table, float* __restrict__ out) {
  extern __shared__ float sm[];
  float* tab = sm;                 // 6728
  float* qs  = tab + 6728;         // 256    [r*4+d]
  float* vs  = qs + 256;           // 8192   [m*64+e]
  float* Pt  = vs + 8192;          // 128*PSTR [m][r] transposed
  float* Sr  = Pt + 128 * PSTR;    // 64 row sums

  const int tile = blockIdx.x, g = blockIdx.y, b = blockIdx.z;
  const int n0 = tile * 64;
  const int t = threadIdx.x;
  const int lane = t & 31, w = t >> 5;

  for (int i = t; i < TBL; i += 256) tab[i] = rel_table[g * TBL + i];
  qs[t] = g_qp[b][g][n0 + (t >> 2)][t & 3];

  ull acc[4][2];
#pragma unroll
  for (int i = 0; i < 4; i++) { acc[i][0] = 0ull; acc[i][1] = 0ull; }
  float srow[8];
#pragma unroll
  for (int k = 0; k < 8; k++) srow[k] = 0.f;

  const int rbase = w * 8;                         // logits rows
  const int rpv = (w & 1) * 32 + (lane & 7) * 4;   // PV rows
  const int cpv = (w >> 1) * 16 + (lane >> 3) * 4; // PV cols

  int ar[8];
#pragma unroll
  for (int k = 0; k < 8; k++) ar[k] = rel_a(n0 + rbase + k) + RELC;

  __syncthreads();

  for (int ch = 0; ch < 8; ch++) {
    const int m0 = ch * 128;
    if (ch) __syncthreads();

    const float4* vsrc = (const float4*)&g_vp[b][g][m0][0];
#pragma unroll
    for (int i = 0; i < 8; i++)
      ((float4*)vs)[t + i * 256] = vsrc[t + i * 256];

#pragma unroll
    for (int j = 0; j < 4; j++) {
      const int m = lane + 32 * j;
      const int am = rel_a(m0 + m);
      float4 kv = *(const float4*)&g_kp[b][g][m0 + m][0];
      float e_buf[8];
#pragma unroll
      for (int k = 0; k < 8; k++) {
        float4 qv = *(float4*)&qs[(rbase + k) * 4];
        float l = 0.5f * (qv.x * kv.x + qv.y * kv.y + qv.z * kv.z + qv.w * kv.w)
                  + tab[ar[k] - am];
        float e = __expf(l);
        e_buf[k] = e;
        srow[k] += e;
      }
      *(float4*)&Pt[m * PSTR + rbase]     = make_float4(e_buf[0], e_buf[1], e_buf[2], e_buf[3]);
      *(float4*)&Pt[m * PSTR + rbase + 4] = make_float4(e_buf[4], e_buf[5], e_buf[6], e_buf[7]);
    }
    __syncthreads();

#pragma unroll 4
    for (int m = 0; m < 128; m++) {
      float4 pr = *(float4*)&Pt[m * PSTR + rpv];
      float4 vv = *(float4*)&vs[m * 64 + cpv];
      ull v01 = pack2(vv.x, vv.y), v23 = pack2(vv.z, vv.w);
      ull p0 = pack2(pr.x, pr.x), p1 = pack2(pr.y, pr.y);
      ull p2 = pack2(pr.z, pr.z), p3 = pack2(pr.w, pr.w);
      ffma2(acc[0][0], p0, v01); ffma2(acc[0][1], p0, v23);
      ffma2(acc[1][0], p1, v01); ffma2(acc[1][1], p1, v23);
      ffma2(acc[2][0], p2, v01); ffma2(acc[2][1], p2, v23);
      ffma2(acc[3][0], p3, v01); ffma2(acc[3][1], p3, v23);
    }
  }

#pragma unroll
  for (int k = 0; k < 8; k++) {
    float s = srow[k];
    s += __shfl_xor_sync(0xffffffffu, s, 16);
    s += __shfl_xor_sync(0xffffffffu, s, 8);
    s += __shfl_xor_sync(0xffffffffu, s, 4);
    s += __shfl_xor_sync(0xffffffffu, s, 2);
    s += __shfl_xor_sync(0xffffffffu, s, 1);
    if (lane == 0) Sr[rbase + k] = s;
  }
  __syncthreads();

  const int d = w >> 1, sy = lane >> 3;
#pragma unroll
  for (int i = 0; i < 4; i++) {
    int r = rpv + i;
    float inv = 1.f / Sr[r];
    float a0, a1, a2, a3;
    unpack2(acc[i][0], a0, a1);
    unpack2(acc[i][1], a2, a3);
    int n = n0 + r;
    int tt = n >> 8, hy = (n >> 4) & 15, wx = n & 15;
    size_t off = ((((size_t)b * 128 + g * 4 + d) * 4 + tt) * 64 + hy * 4 + sy) * 64 + wx * 4;
    *(float4*)&out[off] = make_float4(a0 * inv, a1 * inv, a2 * inv, a3 * inv);
  }
}

// ============================================================
extern "C" void kernel_launch(void* const* d_in, const int* in_sizes, int n_in,
                              void* d_out, int out_size) {
  (void)in_sizes; (void)n_in; (void)out_size;
  const float* x   = (const float*)d_in[0];
  const float* Wq  = (const float*)d_in[1];
  const float* Wk  = (const float*)d_in[2];
  const float* Wv  = (const float*)d_in[3];
  const float* gqg = (const float*)d_in[4];
  const float* gqb = (const float*)d_in[5];
  const float* gkg = (const float*)d_in[6];
  const float* gkb = (const float*)d_in[7];
  const float* gvg = (const float*)d_in[8];
  const float* gvb = (const float*)d_in[9];
  const float* rel_table = (const float*)d_in[10];
  float* out = (float*)d_out;

  const int smem = (6728 + 256 + 8192 + 128 * PSTR + 64) * sizeof(float);  // 95776
  cudaFuncSetAttribute(attn_kernel, cudaFuncAttributeMaxDynamicSharedMemorySize, smem);

  pool_x_kernel<<<dim3(128, 2), 256>>>(x);
  gram_kernel<<<dim3(64, 2), 256>>>(x);
  gram_reduce_kernel<<<dim3(128, 2), 128>>>();
  fold_kernel<<<dim3(16, 3, 2), 256>>>(Wq, Wk, Wv, gqg, gqb, gkg, gkb, gvg, gvb);
  qk_gemm_kernel<<<dim3(16, 2, 2), 256>>>();
  v_gemm_kernel<<<dim3(256, 2), 256>>>(x);
  attn_kernel<<<dim3(16, 32, 2), 256, smem>>>(rel_table, out);
}

// round 13
// speedup vs baseline: 1.2250x; 1.0027x over previous
#include <cuda_runtime.h>
#include <cstdint>

#define BB 2
#define NH 32
#define SP 16384   // T*H*W
#define NN 1024
#define TBL 6727   // 7*31*31
#define EPS 1e-5f
#define PSTR 68    // Pt row stride (float4-aligned, conflict-free phases)
#define RELC 3363  // 3*961 + 15*31 + 15

typedef unsigned long long ull;

// ---- scratch (device globals; no allocation allowed) ----
__device__ float g_xpool[BB][128][NN];        // patch-pooled x
__device__ float g_Gpart[BB][64][128][128];   // Gram partials (8MB)
__device__ float g_G[BB][128][128];           // Gram
__device__ float g_xbar[BB][128];             // spatial mean of x
__device__ float g_Wf[3][BB][128][128];       // folded weights (GN absorbed)
__device__ float g_bf[3][BB][128];            // folded bias
__device__ float g_qp[BB][NH][NN][4];         // pooled normalized queries
__device__ float g_kp[BB][NH][NN][4];         // pooled normalized keys
__device__ float g_vp[BB][NH][NN][64];        // normalized values [n][e]

__device__ __forceinline__ void ffma2(ull& d, ull a, ull b) {
  asm("fma.rn.f32x2 %0, %1, %2, %0;" : "+l"(d) : "l"(a), "l"(b));
}
__device__ __forceinline__ ull pack2(float lo, float hi) {
  ull r; asm("mov.b64 %0, {%1, %2};" : "=l"(r) : "f"(lo), "f"(hi)); return r;
}
__device__ __forceinline__ void unpack2(ull v, float& lo, float& hi) {
  asm("mov.b64 {%0, %1}, %2;" : "=f"(lo), "=f"(hi) : "l"(v));
}
// a(n) for the affine rel-position index: idx(r,m) = a(r) - a(m) + RELC
__device__ __forceinline__ int rel_a(int n) {
  return (n >> 8) * 961 + ((n >> 4) & 15) * 31 + (n & 15);
}

// ============================================================
// K1: patch-pool x -> g_xpool[b][c][n]
// ============================================================
__global__ __launch_bounds__(256) void pool_x_kernel(const float* __restrict__ x) {
  const int c = blockIdx.x, b = blockIdx.y;
  const float* xp = x + ((size_t)b * 128 + c) * SP;
#pragma unroll
  for (int it = 0; it < 4; it++) {
    int n = threadIdx.x + it * 256;
    int tt = n >> 8, hy = (n >> 4) & 15, wx = n & 15;
    const float* base = xp + (tt * 64 + hy * 4) * 64 + wx * 4;
    float s = 0.f;
#pragma unroll
    for (int sy = 0; sy < 4; sy++) {
      float4 v = *(const float4*)(base + sy * 64);
      s += (v.x + v.y) + (v.z + v.w);
    }
    g_xpool[b][c][n] = s * (1.f / 16.f);
  }
}

// ============================================================
// K2: Gram partials
// ============================================================
__global__ __launch_bounds__(256) void gram_kernel(const float* __restrict__ x) {
  const int b = blockIdx.y;
  const int s0 = blockIdx.x * 256;
  __shared__ float xsm[16][132];
  const int t = threadIdx.x, tx = t & 15, ty = t >> 4;
  ull acc[8][4];
#pragma unroll
  for (int i = 0; i < 8; i++)
#pragma unroll
    for (int j = 0; j < 4; j++) acc[i][j] = 0ull;
  const float* xb = x + (size_t)b * 128 * SP;
  for (int ks = 0; ks < 16; ks++) {
#pragma unroll
    for (int i = 0; i < 2; i++) {
      int idx = t + i * 256;
      int c = idx >> 2, sq = idx & 3;
      float4 v = *(const float4*)&xb[(size_t)c * SP + s0 + ks * 16 + sq * 4];
      xsm[sq * 4 + 0][c] = v.x; xsm[sq * 4 + 1][c] = v.y;
      xsm[sq * 4 + 2][c] = v.z; xsm[sq * 4 + 3][c] = v.w;
    }
    __syncthreads();
#pragma unroll
    for (int k = 0; k < 16; k++) {
      float4 a0 = *(float4*)&xsm[k][ty * 8];
      float4 a1 = *(float4*)&xsm[k][ty * 8 + 4];
      float4 b0 = *(float4*)&xsm[k][tx * 8];
      float4 b1 = *(float4*)&xsm[k][tx * 8 + 4];
      ull p01 = pack2(b0.x, b0.y), p23 = pack2(b0.z, b0.w);
      ull p45 = pack2(b1.x, b1.y), p67 = pack2(b1.z, b1.w);
      float av[8] = {a0.x, a0.y, a0.z, a0.w, a1.x, a1.y, a1.z, a1.w};
#pragma unroll
      for (int i = 0; i < 8; i++) {
        ull ad = pack2(av[i], av[i]);
        ffma2(acc[i][0], ad, p01); ffma2(acc[i][1], ad, p23);
        ffma2(acc[i][2], ad, p45); ffma2(acc[i][3], ad, p67);
      }
    }
    __syncthreads();
  }
  float* gp = &g_Gpart[b][blockIdx.x][0][0];
#pragma unroll
  for (int i = 0; i < 8; i++) {
    int row = ty * 8 + i;
    float r0, r1, r2, r3, r4, r5, r6, r7;
    unpack2(acc[i][0], r0, r1); unpack2(acc[i][1], r2, r3);
    unpack2(acc[i][2], r4, r5); unpack2(acc[i][3], r6, r7);
    *(float4*)&gp[row * 128 + tx * 8]     = make_float4(r0, r1, r2, r3);
    *(float4*)&gp[row * 128 + tx * 8 + 4] = make_float4(r4, r5, r6, r7);
  }
}

// ============================================================
// K3: reduce Gram partials + xbar
// ============================================================
__global__ __launch_bounds__(128) void gram_reduce_kernel() {
  const int c = blockIdx.x, b = blockIdx.y;
  const int t = threadIdx.x;
  float s = 0.f;
  for (int p = 0; p < 64; p++) s += g_Gpart[b][p][c][t];
  g_G[b][c][t] = s;
  float xs = 0.f;
#pragma unroll
  for (int i = 0; i < 8; i++) xs += g_xpool[b][c][t + i * 128];
  __shared__ float red[128];
  red[t] = xs;
  __syncthreads();
  for (int str = 64; str > 0; str >>= 1) {
    if (t < str) red[t] += red[t + str];
    __syncthreads();
  }
  if (t == 0) g_xbar[b][c] = red[0] * (1.f / 1024.f);
}

// ============================================================
// K4: fold GN stats into weights. v3: warp-per-channel with FOUR
// independent accumulation chains (j, j+32, j+64, j+96) -> 16 LDGs
// in flight per iteration, no serial latency chain.
// grid (16 c-octets, 3 z, 2 b), 256 threads = 8 warps = 8 channels.
// ============================================================
__global__ __launch_bounds__(256) void fold_kernel(
    const float* __restrict__ Wq, const float* __restrict__ Wk,
    const float* __restrict__ Wv,
    const float* __restrict__ gqg, const float* __restrict__ gqb,
    const float* __restrict__ gkg, const float* __restrict__ gkb,
    const float* __restrict__ gvg, const float* __restrict__ gvb) {
  const int coct = blockIdx.x, z = blockIdx.y, b = blockIdx.z;
  const int t = threadIdx.x, lane = t & 31, w = t >> 5;
  const float* Wm = (z == 0) ? Wq : (z == 1 ? Wk : Wv);
  const float* ga = (z == 0) ? gqg : (z == 1 ? gkg : gvg);
  const float* be = (z == 0) ? gqb : (z == 1 ? gkb : gvb);
  __shared__ float Wc[8][128];
  __shared__ float s_s[8], s_m[8];
  __shared__ float muv[2], rsv[2];
#pragma unroll
  for (int i = 0; i < 4; i++) {
    int idx = t + i * 256;
    Wc[idx >> 7][idx & 127] = Wm[(coct * 8 + (idx >> 7)) * 128 + (idx & 127)];
  }
  __syncthreads();

  // warp w handles channel c = coct*8 + w
  float wl[4], sxl[4];
#pragma unroll
  for (int i = 0; i < 4; i++) {
    wl[i] = Wc[w][lane + 32 * i];
    sxl[i] = g_xbar[b][lane + 32 * i];
  }
  float m = wl[0] * sxl[0] + wl[1] * sxl[1] + wl[2] * sxl[2] + wl[3] * sxl[3];

  // quadratic form: 4 independent chains over j-rows
  float s0 = 0.f, s1 = 0.f, s2 = 0.f, s3 = 0.f;
  const float* Gb = &g_G[b][0][0];
#pragma unroll 4
  for (int j = 0; j < 32; j++) {
    const float* G0 = Gb + j * 128;
    const float* G1 = Gb + (j + 32) * 128;
    const float* G2 = Gb + (j + 64) * 128;
    const float* G3 = Gb + (j + 96) * 128;
    float d0 = wl[0] * G0[lane] + wl[1] * G0[lane + 32] +
               wl[2] * G0[lane + 64] + wl[3] * G0[lane + 96];
    float d1 = wl[0] * G1[lane] + wl[1] * G1[lane + 32] +
               wl[2] * G1[lane + 64] + wl[3] * G1[lane + 96];
    float d2 = wl[0] * G2[lane] + wl[1] * G2[lane + 32] +
               wl[2] * G2[lane + 64] + wl[3] * G2[lane + 96];
    float d3 = wl[0] * G3[lane] + wl[1] * G3[lane + 32] +
               wl[2] * G3[lane + 64] + wl[3] * G3[lane + 96];
    s0 = fmaf(Wc[w][j], d0, s0);
    s1 = fmaf(Wc[w][j + 32], d1, s1);
    s2 = fmaf(Wc[w][j + 64], d2, s2);
    s3 = fmaf(Wc[w][j + 96], d3, s3);
  }
  float s = (s0 + s1) + (s2 + s3);
#pragma unroll
  for (int o = 16; o > 0; o >>= 1) {
    s += __shfl_xor_sync(0xffffffffu, s, o);
    m += __shfl_xor_sync(0xffffffffu, m, o);
  }
  if (lane == 0) { s_s[w] = s; s_m[w] = m; }
  __syncthreads();
  if (t < 2) {
    float mm = 0.25f * (s_m[t * 4] + s_m[t * 4 + 1] + s_m[t * 4 + 2] + s_m[t * 4 + 3]);
    float e2 = (s_s[t * 4] + s_s[t * 4 + 1] + s_s[t * 4 + 2] + s_s[t * 4 + 3]) *
               (1.f / (4.f * (float)SP));
    muv[t] = mm;
    rsv[t] = rsqrtf(e2 - mm * mm + EPS);
  }
  __syncthreads();
#pragma unroll
  for (int i = 0; i < 4; i++) {
    int idx = t + i * 256;
    int row = idx >> 7, k = idx & 127;
    int c = coct * 8 + row, lg = row >> 2;
    g_Wf[z][b][c][k] = rsv[lg] * ga[c] * Wc[row][k];
  }
  if (t < 8) {
    int c = coct * 8 + t, lg = t >> 2;
    g_bf[z][b][c] = be[c] - muv[lg] * rsv[lg] * ga[c];
  }
}

// ============================================================
// K5: pooled q/k GEMM
// ============================================================
__global__ __launch_bounds__(256) void qk_gemm_kernel() {
  const int z = blockIdx.y, b = blockIdx.z;
  const int n0 = blockIdx.x * 64;
  const float* Wm = &g_Wf[z][b][0][0];
  __shared__ float Ws[16][128];
  __shared__ float xs[16][64];
  const int t = threadIdx.x, tx = t & 15, ty = t >> 4;
  float acc[8][4];
#pragma unroll
  for (int i = 0; i < 8; i++) { acc[i][0]=0.f; acc[i][1]=0.f; acc[i][2]=0.f; acc[i][3]=0.f; }
  for (int kc = 0; kc < 128; kc += 16) {
    {
      int o = t >> 1, koff = (t & 1) * 8;
      const float* wp = Wm + o * 128 + kc + koff;
      float4 w0 = *(const float4*)wp;
      float4 w1 = *(const float4*)(wp + 4);
      Ws[koff + 0][o] = w0.x; Ws[koff + 1][o] = w0.y;
      Ws[koff + 2][o] = w0.z; Ws[koff + 3][o] = w0.w;
      Ws[koff + 4][o] = w1.x; Ws[koff + 5][o] = w1.y;
      Ws[koff + 6][o] = w1.z; Ws[koff + 7][o] = w1.w;
    }
    *(float4*)&xs[ty][tx * 4] = *(const float4*)&g_xpool[b][kc + ty][n0 + tx * 4];
    __syncthreads();
#pragma unroll
    for (int k = 0; k < 16; k++) {
      float4 a0 = *(float4*)&Ws[k][ty * 8];
      float4 a1 = *(float4*)&Ws[k][ty * 8 + 4];
      float4 bv = *(float4*)&xs[k][tx * 4];
      float av[8] = {a0.x, a0.y, a0.z, a0.w, a1.x, a1.y, a1.z, a1.w};
#pragma unroll
      for (int i = 0; i < 8; i++) {
        acc[i][0] = fmaf(av[i], bv.x, acc[i][0]);
        acc[i][1] = fmaf(av[i], bv.y, acc[i][1]);
        acc[i][2] = fmaf(av[i], bv.z, acc[i][2]);
        acc[i][3] = fmaf(av[i], bv.w, acc[i][3]);
      }
    }
    __syncthreads();
  }
#pragma unroll
  for (int i = 0; i < 8; i++) {
    int c = ty * 8 + i, g = c >> 2, d = c & 3;
    float bias = g_bf[z][b][c];
    float* dst = (z == 0) ? &g_qp[b][g][0][0] : &g_kp[b][g][0][0];
#pragma unroll
    for (int jj = 0; jj < 4; jj++)
      dst[(n0 + tx * 4 + jj) * 4 + d] = acc[i][jj] + bias;
  }
}

// ============================================================
// K6: V GEMM full-res
// ============================================================
__global__ __launch_bounds__(256) void v_gemm_kernel(const float* __restrict__ x) {
  const int b = blockIdx.y;
  const int s0 = blockIdx.x * 64;
  const float* Wm = &g_Wf[2][b][0][0];
  __shared__ float Ws[16][128];
  __shared__ float xs[16][64];
  const int t = threadIdx.x, tx = t & 15, ty = t >> 4;
  ull acc[8][2];
#pragma unroll
  for (int i = 0; i < 8; i++) { acc[i][0] = 0ull; acc[i][1] = 0ull; }
  const float* xb = x + (size_t)b * 128 * SP;
  for (int kc = 0; kc < 128; kc += 16) {
    {
      int o = t >> 1, koff = (t & 1) * 8;
      const float* wp = Wm + o * 128 + kc + koff;
      float4 w0 = *(const float4*)wp;
      float4 w1 = *(const float4*)(wp + 4);
      Ws[koff + 0][o] = w0.x; Ws[koff + 1][o] = w0.y;
      Ws[koff + 2][o] = w0.z; Ws[koff + 3][o] = w0.w;
      Ws[koff + 4][o] = w1.x; Ws[koff + 5][o] = w1.y;
      Ws[koff + 6][o] = w1.z; Ws[koff + 7][o] = w1.w;
    }
    *(float4*)&xs[ty][tx * 4] = *(const float4*)&xb[(size_t)(kc + ty) * SP + s0 + tx * 4];
    __syncthreads();
#pragma unroll
    for (int k = 0; k < 16; k++) {
      float4 a0 = *(float4*)&Ws[k][ty * 8];
      float4 a1 = *(float4*)&Ws[k][ty * 8 + 4];
      float4 bv = *(float4*)&xs[k][tx * 4];
      ull b01 = pack2(bv.x, bv.y), b23 = pack2(bv.z, bv.w);
      float av[8] = {a0.x, a0.y, a0.z, a0.w, a1.x, a1.y, a1.z, a1.w};
#pragma unroll
      for (int i = 0; i < 8; i++) {
        ull ad = pack2(av[i], av[i]);
        ffma2(acc[i][0], ad, b01);
        ffma2(acc[i][1], ad, b23);
      }
    }
    __syncthreads();
  }
  const int row = blockIdx.x;
  const int tt = row >> 6, hrow = row & 63, hy = hrow >> 2, sy = hrow & 3;
  const int n = (tt * 16 + hy) * 16 + tx;
#pragma unroll
  for (int i = 0; i < 8; i++) {
    int c = ty * 8 + i, g = c >> 2, d = c & 3;
    float bias = g_bf[2][b][c];
    float r0, r1, r2, r3;
    unpack2(acc[i][0], r0, r1);
    unpack2(acc[i][1], r2, r3);
    *(float4*)&g_vp[b][g][n][d * 16 + sy * 4] =
        make_float4(r0 + bias, r1 + bias, r2 + bias, r3 + bias);
  }
}

// ============================================================
// K7: fused attention. Affine rel_index (zero LDG), qv hoisted per chunk.
// ============================================================
__global__ __launch_bounds__(256, 2) void attn_kernel(
    const float* __restrict__ rel_table, float* __restrict__ out) {
  extern __shared__ float sm[];
  float* tab = sm;                 // 6728
  float* qs  = tab + 6728;         // 256    [r*4+d]
  float* vs  = qs + 256;           // 8192   [m*64+e]
  float* Pt  = vs + 8192;          // 128*PSTR [m][r] transposed
  float* Sr  = Pt + 128 * PSTR;    // 64 row sums

  const int tile = blockIdx.x, g = blockIdx.y, b = blockIdx.z;
  const int n0 = tile * 64;
  const int t = threadIdx.x;
  const int lane = t & 31, w = t >> 5;

  for (int i = t; i < TBL; i += 256) tab[i] = rel_table[g * TBL + i];
  qs[t] = g_qp[b][g][n0 + (t >> 2)][t & 3];

  ull acc[4][2];
#pragma unroll
  for (int i = 0; i < 4; i++) { acc[i][0] = 0ull; acc[i][1] = 0ull; }
  float srow[8];
#pragma unroll
  for (int k = 0; k < 8; k++) srow[k] = 0.f;

  const int rbase = w * 8;                         // logits rows
  const int rpv = (w & 1) * 32 + (lane & 7) * 4;   // PV rows
  const int cpv = (w >> 1) * 16 + (lane >> 3) * 4; // PV cols

  int ar[8];
#pragma unroll
  for (int k = 0; k < 8; k++) ar[k] = rel_a(n0 + rbase + k) + RELC;

  __syncthreads();

  for (int ch = 0; ch < 8; ch++) {
    const int m0 = ch * 128;
    if (ch) __syncthreads();

    const float4* vsrc = (const float4*)&g_vp[b][g][m0][0];
#pragma unroll
    for (int i = 0; i < 8; i++)
      ((float4*)vs)[t + i * 256] = vsrc[t + i * 256];

    // hoisted row queries for this warp's 8 rows
    float4 qv[8];
#pragma unroll
    for (int k = 0; k < 8; k++) qv[k] = *(float4*)&qs[(rbase + k) * 4];

#pragma unroll
    for (int j = 0; j < 4; j++) {
      const int m = lane + 32 * j;
      const int am = rel_a(m0 + m);
      float4 kv = *(const float4*)&g_kp[b][g][m0 + m][0];
      float e_buf[8];
#pragma unroll
      for (int k = 0; k < 8; k++) {
        float l = 0.5f * (qv[k].x * kv.x + qv[k].y * kv.y + qv[k].z * kv.z + qv[k].w * kv.w)
                  + tab[ar[k] - am];
        float e = __expf(l);
        e_buf[k] = e;
        srow[k] += e;
      }
      *(float4*)&Pt[m * PSTR + rbase]     = make_float4(e_buf[0], e_buf[1], e_buf[2], e_buf[3]);
      *(float4*)&Pt[m * PSTR + rbase + 4] = make_float4(e_buf[4], e_buf[5], e_buf[6], e_buf[7]);
    }
    __syncthreads();

#pragma unroll 4
    for (int m = 0; m < 128; m++) {
      float4 pr = *(float4*)&Pt[m * PSTR + rpv];
      float4 vv = *(float4*)&vs[m * 64 + cpv];
      ull v01 = pack2(vv.x, vv.y), v23 = pack2(vv.z, vv.w);
      ull p0 = pack2(pr.x, pr.x), p1 = pack2(pr.y, pr.y);
      ull p2 = pack2(pr.z, pr.z), p3 = pack2(pr.w, pr.w);
      ffma2(acc[0][0], p0, v01); ffma2(acc[0][1], p0, v23);
      ffma2(acc[1][0], p1, v01); ffma2(acc[1][1], p1, v23);
      ffma2(acc[2][0], p2, v01); ffma2(acc[2][1], p2, v23);
      ffma2(acc[3][0], p3, v01); ffma2(acc[3][1], p3, v23);
    }
  }

#pragma unroll
  for (int k = 0; k < 8; k++) {
    float s = srow[k];
    s += __shfl_xor_sync(0xffffffffu, s, 16);
    s += __shfl_xor_sync(0xffffffffu, s, 8);
    s += __shfl_xor_sync(0xffffffffu, s, 4);
    s += __shfl_xor_sync(0xffffffffu, s, 2);
    s += __shfl_xor_sync(0xffffffffu, s, 1);
    if (lane == 0) Sr[rbase + k] = s;
  }
  __syncthreads();

  const int d = w >> 1, sy = lane >> 3;
#pragma unroll
  for (int i = 0; i < 4; i++) {
    int r = rpv + i;
    float inv = 1.f / Sr[r];
    float a0, a1, a2, a3;
    unpack2(acc[i][0], a0, a1);
    unpack2(acc[i][1], a2, a3);
    int n = n0 + r;
    int tt = n >> 8, hy = (n >> 4) & 15, wx = n & 15;
    size_t off = ((((size_t)b * 128 + g * 4 + d) * 4 + tt) * 64 + hy * 4 + sy) * 64 + wx * 4;
    *(float4*)&out[off] = make_float4(a0 * inv, a1 * inv, a2 * inv, a3 * inv);
  }
}

// ============================================================
extern "C" void kernel_launch(void* const* d_in, const int* in_sizes, int n_in,
                              void* d_out, int out_size) {
  (void)in_sizes; (void)n_in; (void)out_size;
  const float* x   = (const float*)d_in[0];
  const float* Wq  = (const float*)d_in[1];
  const float* Wk  = (const float*)d_in[2];
  const float* Wv  = (const float*)d_in[3];
  const float* gqg = (const float*)d_in[4];
  const float* gqb = (const float*)d_in[5];
  const float* gkg = (const float*)d_in[6];
  const float* gkb = (const float*)d_in[7];
  const float* gvg = (const float*)d_in[8];
  const float* gvb = (const float*)d_in[9];
  const float* rel_table = (const float*)d_in[10];
  float* out = (float*)d_out;

  const int smem = (6728 + 256 + 8192 + 128 * PSTR + 64) * sizeof(float);  // 95776
  cudaFuncSetAttribute(attn_kernel, cudaFuncAttributeMaxDynamicSharedMemorySize, smem);

  pool_x_kernel<<<dim3(128, 2), 256>>>(x);
  gram_kernel<<<dim3(64, 2), 256>>>(x);
  gram_reduce_kernel<<<dim3(128, 2), 128>>>();
  fold_kernel<<<dim3(16, 3, 2), 256>>>(Wq, Wk, Wv, gqg, gqb, gkg, gkb, gvg, gvb);
  qk_gemm_kernel<<<dim3(16, 2, 2), 256>>>();
  v_gemm_kernel<<<dim3(256, 2), 256>>>(x);
  attn_kernel<<<dim3(16, 32, 2), 256, smem>>>(rel_table, out);
}

// round 15
// speedup vs baseline: 1.2569x; 1.0261x over previous
#include <cuda_runtime.h>
#include <cstdint>

#define BB 2
#define NH 32
#define SP 16384   // T*H*W
#define NN 1024
#define TBL 6727   // 7*31*31
#define EPS 1e-5f
#define PSTR 68    // Pt row stride (float4-aligned, conflict-free phases)
#define RELC 3363  // 3*961 + 15*31 + 15

typedef unsigned long long ull;

// ---- scratch (device globals; no allocation allowed) ----
__device__ float g_xpool[BB][128][NN];        // patch-pooled x
__device__ float g_Gpart[BB][64][128][128];   // Gram partials (8MB)
__device__ float g_G[BB][128][128];           // Gram
__device__ float g_xbar[BB][128];             // spatial mean of x
__device__ float g_scale[3][BB][128];         // per-channel GN scale (rs*gamma)
__device__ float g_bias[3][BB][128];          // per-channel GN bias
__device__ float g_qp[BB][NH][NN][4];         // pooled normalized queries
__device__ float g_kp[BB][NH][NN][4];         // pooled normalized keys
__device__ float g_vp[BB][NH][NN][64];        // normalized values [n][e]

__device__ __forceinline__ void ffma2(ull& d, ull a, ull b) {
  asm("fma.rn.f32x2 %0, %1, %2, %0;" : "+l"(d) : "l"(a), "l"(b));
}
__device__ __forceinline__ ull pack2(float lo, float hi) {
  ull r; asm("mov.b64 %0, {%1, %2};" : "=l"(r) : "f"(lo), "f"(hi)); return r;
}
__device__ __forceinline__ void unpack2(ull v, float& lo, float& hi) {
  asm("mov.b64 {%0, %1}, %2;" : "=f"(lo), "=f"(hi) : "l"(v));
}
// a(n) for the affine rel-position index: idx(r,m) = a(r) - a(m) + RELC
__device__ __forceinline__ int rel_a(int n) {
  return (n >> 8) * 961 + ((n >> 4) & 15) * 31 + (n & 15);
}

// ============================================================
// K1: patch-pool x -> g_xpool[b][c][n]
// ============================================================
__global__ __launch_bounds__(256) void pool_x_kernel(const float* __restrict__ x) {
  const int c = blockIdx.x, b = blockIdx.y;
  const float* xp = x + ((size_t)b * 128 + c) * SP;
#pragma unroll
  for (int it = 0; it < 4; it++) {
    int n = threadIdx.x + it * 256;
    int tt = n >> 8, hy = (n >> 4) & 15, wx = n & 15;
    const float* base = xp + (tt * 64 + hy * 4) * 64 + wx * 4;
    float s = 0.f;
#pragma unroll
    for (int sy = 0; sy < 4; sy++) {
      float4 v = *(const float4*)(base + sy * 64);
      s += (v.x + v.y) + (v.z + v.w);
    }
    g_xpool[b][c][n] = s * (1.f / 16.f);
  }
}

// ============================================================
// K2: Gram partials
// ============================================================
__global__ __launch_bounds__(256) void gram_kernel(const float* __restrict__ x) {
  const int b = blockIdx.y;
  const int s0 = blockIdx.x * 256;
  __shared__ float xsm[16][132];
  const int t = threadIdx.x, tx = t & 15, ty = t >> 4;
  ull acc[8][4];
#pragma unroll
  for (int i = 0; i < 8; i++)
#pragma unroll
    for (int j = 0; j < 4; j++) acc[i][j] = 0ull;
  const float* xb = x + (size_t)b * 128 * SP;
  for (int ks = 0; ks < 16; ks++) {
#pragma unroll
    for (int i = 0; i < 2; i++) {
      int idx = t + i * 256;
      int c = idx >> 2, sq = idx & 3;
      float4 v = *(const float4*)&xb[(size_t)c * SP + s0 + ks * 16 + sq * 4];
      xsm[sq * 4 + 0][c] = v.x; xsm[sq * 4 + 1][c] = v.y;
      xsm[sq * 4 + 2][c] = v.z; xsm[sq * 4 + 3][c] = v.w;
    }
    __syncthreads();
#pragma unroll
    for (int k = 0; k < 16; k++) {
      float4 a0 = *(float4*)&xsm[k][ty * 8];
      float4 a1 = *(float4*)&xsm[k][ty * 8 + 4];
      float4 b0 = *(float4*)&xsm[k][tx * 8];
      float4 b1 = *(float4*)&xsm[k][tx * 8 + 4];
      ull p01 = pack2(b0.x, b0.y), p23 = pack2(b0.z, b0.w);
      ull p45 = pack2(b1.x, b1.y), p67 = pack2(b1.z, b1.w);
      float av[8] = {a0.x, a0.y, a0.z, a0.w, a1.x, a1.y, a1.z, a1.w};
#pragma unroll
      for (int i = 0; i < 8; i++) {
        ull ad = pack2(av[i], av[i]);
        ffma2(acc[i][0], ad, p01); ffma2(acc[i][1], ad, p23);
        ffma2(acc[i][2], ad, p45); ffma2(acc[i][3], ad, p67);
      }
    }
    __syncthreads();
  }
  float* gp = &g_Gpart[b][blockIdx.x][0][0];
#pragma unroll
  for (int i = 0; i < 8; i++) {
    int row = ty * 8 + i;
    float r0, r1, r2, r3, r4, r5, r6, r7;
    unpack2(acc[i][0], r0, r1); unpack2(acc[i][1], r2, r3);
    unpack2(acc[i][2], r4, r5); unpack2(acc[i][3], r6, r7);
    *(float4*)&gp[row * 128 + tx * 8]     = make_float4(r0, r1, r2, r3);
    *(float4*)&gp[row * 128 + tx * 8 + 4] = make_float4(r4, r5, r6, r7);
  }
}

// ============================================================
// K3: reduce Gram partials + xbar
// ============================================================
__global__ __launch_bounds__(128) void gram_reduce_kernel() {
  const int c = blockIdx.x, b = blockIdx.y;
  const int t = threadIdx.x;
  float s = 0.f;
  for (int p = 0; p < 64; p++) s += g_Gpart[b][p][c][t];
  g_G[b][c][t] = s;
  float xs = 0.f;
#pragma unroll
  for (int i = 0; i < 8; i++) xs += g_xpool[b][c][t + i * 128];
  __shared__ float red[128];
  red[t] = xs;
  __syncthreads();
  for (int str = 64; str > 0; str >>= 1) {
    if (t < str) red[t] += red[t + str];
    __syncthreads();
  }
  if (t == 0) g_xbar[b][c] = red[0] * (1.f / 1024.f);
}

// ============================================================
// K4: fold v4 -> per-channel scale/bias only (no g_Wf materialization).
// grid (32 groups, 3 z, 2 b) = 192 blocks, 128 threads.
// Thread = G-row j: 32 independent LDG.128 of row j, dotted against
// the group's 4 W rows (smem). Warp w reduces channel w.
// ============================================================
__global__ __launch_bounds__(128) void fold_kernel(
    const float* __restrict__ Wq, const float* __restrict__ Wk,
    const float* __restrict__ Wv,
    const float* __restrict__ gqg, const float* __restrict__ gqb,
    const float* __restrict__ gkg, const float* __restrict__ gkb,
    const float* __restrict__ gvg, const float* __restrict__ gvb) {
  const int g = blockIdx.x, z = blockIdx.y, b = blockIdx.z;
  const int t = threadIdx.x, lane = t & 31, w = t >> 5;
  const float* Wm = (z == 0) ? Wq : (z == 1 ? Wk : Wv);
  const float* ga = (z == 0) ? gqg : (z == 1 ? gkg : gvg);
  const float* be = (z == 0) ? gqb : (z == 1 ? gkb : gvb);
  __shared__ float sw[4][128];   // 4 channel weight rows
  __shared__ float pp[4][128];   // quadratic-form row partials
  __shared__ float qq[4][128];   // mean partials
  __shared__ float s_red[4], m_red[4];

#pragma unroll
  for (int i = 0; i < 4; i++) {
    int idx = t + i * 128;
    sw[idx >> 7][idx & 127] = Wm[(g * 4 + (idx >> 7)) * 128 + (idx & 127)];
  }
  __syncthreads();

  // thread t owns G row j = t: d_c = G[j] . W_c for the 4 channels
  const float* Gj = &g_G[b][t][0];
  float d0 = 0.f, d1 = 0.f, d2 = 0.f, d3 = 0.f;
#pragma unroll 8
  for (int kk = 0; kk < 32; kk++) {
    float4 gv = *(const float4*)&Gj[kk * 4];
    float4 w0 = *(const float4*)&sw[0][kk * 4];
    float4 w1 = *(const float4*)&sw[1][kk * 4];
    float4 w2 = *(const float4*)&sw[2][kk * 4];
    float4 w3 = *(const float4*)&sw[3][kk * 4];
    d0 += gv.x * w0.x + gv.y * w0.y + gv.z * w0.z + gv.w * w0.w;
    d1 += gv.x * w1.x + gv.y * w1.y + gv.z * w1.z + gv.w * w1.w;
    d2 += gv.x * w2.x + gv.y * w2.y + gv.z * w2.z + gv.w * w2.w;
    d3 += gv.x * w3.x + gv.y * w3.y + gv.z * w3.z + gv.w * w3.w;
  }
  const float xb = g_xbar[b][t];
  pp[0][t] = sw[0][t] * d0; qq[0][t] = sw[0][t] * xb;
  pp[1][t] = sw[1][t] * d1; qq[1][t] = sw[1][t] * xb;
  pp[2][t] = sw[2][t] * d2; qq[2][t] = sw[2][t] * xb;
  pp[3][t] = sw[3][t] * d3; qq[3][t] = sw[3][t] * xb;
  __syncthreads();

  // warp w reduces channel w
  {
    float sp = pp[w][lane] + pp[w][lane + 32] + pp[w][lane + 64] + pp[w][lane + 96];
    float sq = qq[w][lane] + qq[w][lane + 32] + qq[w][lane + 64] + qq[w][lane + 96];
#pragma unroll
    for (int o = 16; o > 0; o >>= 1) {
      sp += __shfl_xor_sync(0xffffffffu, sp, o);
      sq += __shfl_xor_sync(0xffffffffu, sq, o);
    }
    if (lane == 0) { s_red[w] = sp; m_red[w] = sq; }
  }
  __syncthreads();

  if (t == 0) {
    float mu = 0.25f * (m_red[0] + m_red[1] + m_red[2] + m_red[3]);
    float e2 = (s_red[0] + s_red[1] + s_red[2] + s_red[3]) * (1.f / (4.f * (float)SP));
    float rs = rsqrtf(e2 - mu * mu + EPS);
#pragma unroll
    for (int c8 = 0; c8 < 4; c8++) {
      int c = g * 4 + c8;
      float sc = rs * ga[c];
      g_scale[z][b][c] = sc;
      g_bias[z][b][c] = be[c] - mu * sc;
    }
  }
}

// ============================================================
// K5: pooled q/k GEMM (raw W, scale folded while staging, bias in epilogue)
// ============================================================
__global__ __launch_bounds__(256) void qk_gemm_kernel(
    const float* __restrict__ Wq, const float* __restrict__ Wk) {
  const int z = blockIdx.y, b = blockIdx.z;
  const int n0 = blockIdx.x * 64;
  const float* Wm = (z == 0) ? Wq : Wk;
  __shared__ float Ws[16][128];
  __shared__ float xs[16][64];
  const int t = threadIdx.x, tx = t & 15, ty = t >> 4;
  const int o_st = t >> 1;
  const float sco = g_scale[z][b][o_st];   // staging row scale (fixed per thread)
  float acc[8][4];
#pragma unroll
  for (int i = 0; i < 8; i++) { acc[i][0]=0.f; acc[i][1]=0.f; acc[i][2]=0.f; acc[i][3]=0.f; }
  for (int kc = 0; kc < 128; kc += 16) {
    {
      int koff = (t & 1) * 8;
      const float* wp = Wm + o_st * 128 + kc + koff;
      float4 w0 = *(const float4*)wp;
      float4 w1 = *(const float4*)(wp + 4);
      Ws[koff + 0][o_st] = w0.x * sco; Ws[koff + 1][o_st] = w0.y * sco;
      Ws[koff + 2][o_st] = w0.z * sco; Ws[koff + 3][o_st] = w0.w * sco;
      Ws[koff + 4][o_st] = w1.x * sco; Ws[koff + 5][o_st] = w1.y * sco;
      Ws[koff + 6][o_st] = w1.z * sco; Ws[koff + 7][o_st] = w1.w * sco;
    }
    *(float4*)&xs[ty][tx * 4] = *(const float4*)&g_xpool[b][kc + ty][n0 + tx * 4];
    __syncthreads();
#pragma unroll
    for (int k = 0; k < 16; k++) {
      float4 a0 = *(float4*)&Ws[k][ty * 8];
      float4 a1 = *(float4*)&Ws[k][ty * 8 + 4];
      float4 bv = *(float4*)&xs[k][tx * 4];
      float av[8] = {a0.x, a0.y, a0.z, a0.w, a1.x, a1.y, a1.z, a1.w};
#pragma unroll
      for (int i = 0; i < 8; i++) {
        acc[i][0] = fmaf(av[i], bv.x, acc[i][0]);
        acc[i][1] = fmaf(av[i], bv.y, acc[i][1]);
        acc[i][2] = fmaf(av[i], bv.z, acc[i][2]);
        acc[i][3] = fmaf(av[i], bv.w, acc[i][3]);
      }
    }
    __syncthreads();
  }
#pragma unroll
  for (int i = 0; i < 8; i++) {
    int c = ty * 8 + i, g = c >> 2, d = c & 3;
    float bias = g_bias[z][b][c];
    float* dst = (z == 0) ? &g_qp[b][g][0][0] : &g_kp[b][g][0][0];
#pragma unroll
    for (int jj = 0; jj < 4; jj++)
      dst[(n0 + tx * 4 + jj) * 4 + d] = acc[i][jj] + bias;
  }
}

// ============================================================
// K6: V GEMM full-res (raw Wv, scale folded at staging)
// ============================================================
__global__ __launch_bounds__(256) void v_gemm_kernel(
    const float* __restrict__ x, const float* __restrict__ Wv) {
  const int b = blockIdx.y;
  const int s0 = blockIdx.x * 64;
  __shared__ float Ws[16][128];
  __shared__ float xs[16][64];
  const int t = threadIdx.x, tx = t & 15, ty = t >> 4;
  const int o_st = t >> 1;
  const float sco = g_scale[2][b][o_st];
  ull acc[8][2];
#pragma unroll
  for (int i = 0; i < 8; i++) { acc[i][0] = 0ull; acc[i][1] = 0ull; }
  const float* xb = x + (size_t)b * 128 * SP;
  for (int kc = 0; kc < 128; kc += 16) {
    {
      int koff = (t & 1) * 8;
      const float* wp = Wv + o_st * 128 + kc + koff;
      float4 w0 = *(const float4*)wp;
      float4 w1 = *(const float4*)(wp + 4);
      Ws[koff + 0][o_st] = w0.x * sco; Ws[koff + 1][o_st] = w0.y * sco;
      Ws[koff + 2][o_st] = w0.z * sco; Ws[koff + 3][o_st] = w0.w * sco;
      Ws[koff + 4][o_st] = w1.x * sco; Ws[koff + 5][o_st] = w1.y * sco;
      Ws[koff + 6][o_st] = w1.z * sco; Ws[koff + 7][o_st] = w1.w * sco;
    }
    *(float4*)&xs[ty][tx * 4] = *(const float4*)&xb[(size_t)(kc + ty) * SP + s0 + tx * 4];
    __syncthreads();
#pragma unroll
    for (int k = 0; k < 16; k++) {
      float4 a0 = *(float4*)&Ws[k][ty * 8];
      float4 a1 = *(float4*)&Ws[k][ty * 8 + 4];
      float4 bv = *(float4*)&xs[k][tx * 4];
      ull b01 = pack2(bv.x, bv.y), b23 = pack2(bv.z, bv.w);
      float av[8] = {a0.x, a0.y, a0.z, a0.w, a1.x, a1.y, a1.z, a1.w};
#pragma unroll
      for (int i = 0; i < 8; i++) {
        ull ad = pack2(av[i], av[i]);
        ffma2(acc[i][0], ad, b01);
        ffma2(acc[i][1], ad, b23);
      }
    }
    __syncthreads();
  }
  const int row = blockIdx.x;
  const int tt = row >> 6, hrow = row & 63, hy = hrow >> 2, sy = hrow & 3;
  const int n = (tt * 16 + hy) * 16 + tx;
#pragma unroll
  for (int i = 0; i < 8; i++) {
    int c = ty * 8 + i, g = c >> 2, d = c & 3;
    float bias = g_bias[2][b][c];
    float r0, r1, r2, r3;
    unpack2(acc[i][0], r0, r1);
    unpack2(acc[i][1], r2, r3);
    *(float4*)&g_vp[b][g][n][d * 16 + sy * 4] =
        make_float4(r0 + bias, r1 + bias, r2 + bias, r3 + bias);
  }
}

// ============================================================
// K7: fused attention. Affine rel_index (zero LDG), qv hoisted per chunk.
// ============================================================
__global__ __launch_bounds__(256, 2) void attn_kernel(
    const float* __restrict__ rel_table, float* __restrict__ out) {
  extern __shared__ float sm[];
  float* tab = sm;                 // 6728
  float* qs  = tab + 6728;         // 256    [r*4+d]
  float* vs  = qs + 256;           // 8192   [m*64+e]
  float* Pt  = vs + 8192;          // 128*PSTR [m][r] transposed
  float* Sr  = Pt + 128 * PSTR;    // 64 row sums

  const int tile = blockIdx.x, g = blockIdx.y, b = blockIdx.z;
  const int n0 = tile * 64;
  const int t = threadIdx.x;
  const int lane = t & 31, w = t >> 5;

  for (int i = t; i < TBL; i += 256) tab[i] = rel_table[g * TBL + i];
  qs[t] = g_qp[b][g][n0 + (t >> 2)][t & 3];

  ull acc[4][2];
#pragma unroll
  for (int i = 0; i < 4; i++) { acc[i][0] = 0ull; acc[i][1] = 0ull; }
  float srow[8];
#pragma unroll
  for (int k = 0; k < 8; k++) srow[k] = 0.f;

  const int rbase = w * 8;                         // logits rows
  const int rpv = (w & 1) * 32 + (lane & 7) * 4;   // PV rows
  const int cpv = (w >> 1) * 16 + (lane >> 3) * 4; // PV cols

  int ar[8];
#pragma unroll
  for (int k = 0; k < 8; k++) ar[k] = rel_a(n0 + rbase + k) + RELC;

  __syncthreads();

  for (int ch = 0; ch < 8; ch++) {
    const int m0 = ch * 128;
    if (ch) __syncthreads();

    const float4* vsrc = (const float4*)&g_vp[b][g][m0][0];
#pragma unroll
    for (int i = 0; i < 8; i++)
      ((float4*)vs)[t + i * 256] = vsrc[t + i * 256];

    float4 qv[8];
#pragma unroll
    for (int k = 0; k < 8; k++) qv[k] = *(float4*)&qs[(rbase + k) * 4];

#pragma unroll
    for (int j = 0; j < 4; j++) {
      const int m = lane + 32 * j;
      const int am = rel_a(m0 + m);
      float4 kv = *(const float4*)&g_kp[b][g][m0 + m][0];
      float e_buf[8];
#pragma unroll
      for (int k = 0; k < 8; k++) {
        float l = 0.5f * (qv[k].x * kv.x + qv[k].y * kv.y + qv[k].z * kv.z + qv[k].w * kv.w)
                  + tab[ar[k] - am];
        float e = __expf(l);
        e_buf[k] = e;
        srow[k] += e;
      }
      *(float4*)&Pt[m * PSTR + rbase]     = make_float4(e_buf[0], e_buf[1], e_buf[2], e_buf[3]);
      *(float4*)&Pt[m * PSTR + rbase + 4] = make_float4(e_buf[4], e_buf[5], e_buf[6], e_buf[7]);
    }
    __syncthreads();

#pragma unroll 4
    for (int m = 0; m < 128; m++) {
      float4 pr = *(float4*)&Pt[m * PSTR + rpv];
      float4 vv = *(float4*)&vs[m * 64 + cpv];
      ull v01 = pack2(vv.x, vv.y), v23 = pack2(vv.z, vv.w);
      ull p0 = pack2(pr.x, pr.x), p1 = pack2(pr.y, pr.y);
      ull p2 = pack2(pr.z, pr.z), p3 = pack2(pr.w, pr.w);
      ffma2(acc[0][0], p0, v01); ffma2(acc[0][1], p0, v23);
      ffma2(acc[1][0], p1, v01); ffma2(acc[1][1], p1, v23);
      ffma2(acc[2][0], p2, v01); ffma2(acc[2][1], p2, v23);
      ffma2(acc[3][0], p3, v01); ffma2(acc[3][1], p3, v23);
    }
  }

#pragma unroll
  for (int k = 0; k < 8; k++) {
    float s = srow[k];
    s += __shfl_xor_sync(0xffffffffu, s, 16);
    s += __shfl_xor_sync(0xffffffffu, s, 8);
    s += __shfl_xor_sync(0xffffffffu, s, 4);
    s += __shfl_xor_sync(0xffffffffu, s, 2);
    s += __shfl_xor_sync(0xffffffffu, s, 1);
    if (lane == 0) Sr[rbase + k] = s;
  }
  __syncthreads();

  const int d = w >> 1, sy = lane >> 3;
#pragma unroll
  for (int i = 0; i < 4; i++) {
    int r = rpv + i;
    float inv = 1.f / Sr[r];
    float a0, a1, a2, a3;
    unpack2(acc[i][0], a0, a1);
    unpack2(acc[i][1], a2, a3);
    int n = n0 + r;
    int tt = n >> 8, hy = (n >> 4) & 15, wx = n & 15;
    size_t off = ((((size_t)b * 128 + g * 4 + d) * 4 + tt) * 64 + hy * 4 + sy) * 64 + wx * 4;
    *(float4*)&out[off] = make_float4(a0 * inv, a1 * inv, a2 * inv, a3 * inv);
  }
}

// ============================================================
extern "C" void kernel_launch(void* const* d_in, const int* in_sizes, int n_in,
                              void* d_out, int out_size) {
  (void)in_sizes; (void)n_in; (void)out_size;
  const float* x   = (const float*)d_in[0];
  const float* Wq  = (const float*)d_in[1];
  const float* Wk  = (const float*)d_in[2];
  const float* Wv  = (const float*)d_in[3];
  const float* gqg = (const float*)d_in[4];
  const float* gqb = (const float*)d_in[5];
  const float* gkg = (const float*)d_in[6];
  const float* gkb = (const float*)d_in[7];
  const float* gvg = (const float*)d_in[8];
  const float* gvb = (const float*)d_in[9];
  const float* rel_table = (const float*)d_in[10];
  float* out = (float*)d_out;

  const int smem = (6728 + 256 + 8192 + 128 * PSTR + 64) * sizeof(float);  // 95776
  cudaFuncSetAttribute(attn_kernel, cudaFuncAttributeMaxDynamicSharedMemorySize, smem);

  pool_x_kernel<<<dim3(128, 2), 256>>>(x);
  gram_kernel<<<dim3(64, 2), 256>>>(x);
  gram_reduce_kernel<<<dim3(128, 2), 128>>>();
  fold_kernel<<<dim3(32, 3, 2), 128>>>(Wq, Wk, Wv, gqg, gqb, gkg, gkb, gvg, gvb);
  qk_gemm_kernel<<<dim3(16, 2, 2), 256>>>(Wq, Wk);
  v_gemm_kernel<<<dim3(256, 2), 256>>>(x, Wv);
  attn_kernel<<<dim3(16, 32, 2), 256, smem>>>(rel_table, out);
}